// round 12
// baseline (speedup 1.0000x reference)
#include <cuda_runtime.h>
#include <cuda_fp16.h>
#include <cstdint>

#define D      512
#define KPROT  1024
#define NMAX   131072
#define NGRP   (NMAX / 128)
#define GAP_TAU 5e-4f

// ---------------- device scratch ----------------
__device__ float  g_protoN [KPROT * D];   // normalized prototypes fp32 (rescoring)
__device__ __half g_protoNh[KPROT * D];   // normalized prototypes fp16 (GEMM)
__device__ float  g_sums   [KPROT * D];
__device__ int    g_counts [KPROT];
__device__ float  g_invn   [NMAX];
__device__ float  g_gap    [NMAX];
__device__ int    g_cand   [NMAX * 2];
__device__ int    g_flag   [NGRP];        // producer CTA done (release)
__device__ unsigned char g_done16[NGRP * 16];  // per (group, warp) consumed marker

// ---------------- helpers ----------------
__device__ __forceinline__ uint32_t smem_u32(const void* p) {
    uint32_t a;
    asm("{ .reg .u64 t; cvta.to.shared.u64 t, %1; cvt.u32.u64 %0, t; }" : "=r"(a) : "l"(p));
    return a;
}
#define SWZ(x) ((x) ^ (((x) >> 3) & 0x70))

#define CP_ASYNC16(dst, src) \
    asm volatile("cp.async.cg.shared.global [%0], [%1], 16;" :: "r"(dst), "l"(src))
#define CP_COMMIT() asm volatile("cp.async.commit_group;")
#define CP_WAIT(n)  asm volatile("cp.async.wait_group %0;" :: "n"(n))

__device__ __forceinline__ void ldsm_x4(uint32_t a[4], uint32_t addr) {
    asm volatile("ldmatrix.sync.aligned.m8n8.x4.shared.b16 {%0,%1,%2,%3}, [%4];"
        : "=r"(a[0]), "=r"(a[1]), "=r"(a[2]), "=r"(a[3]) : "r"(addr));
}
__device__ __forceinline__ void mma_f16f32(float c[4], const uint32_t a[4], uint32_t b0, uint32_t b1) {
    asm volatile(
        "mma.sync.aligned.m16n8k16.row.col.f32.f16.f16.f32 "
        "{%0,%1,%2,%3},{%4,%5,%6,%7},{%8,%9},{%0,%1,%2,%3};"
        : "+f"(c[0]), "+f"(c[1]), "+f"(c[2]), "+f"(c[3])
        : "r"(a[0]), "r"(a[1]), "r"(a[2]), "r"(a[3]), "r"(b0), "r"(b1));
}
__device__ __forceinline__ uint32_t f2_to_h2(float x, float y) {
    __half2 h = __float22half2_rn(make_float2(x, y));
    return *(uint32_t*)&h;
}

// ---- shared k3 body: warp processes one row (gap-gated rescore + atomics) ----
__device__ __forceinline__ void accum_row(const float* __restrict__ emb, int row, int lane) {
    int i1 = g_cand[row * 2 + 0];
    int i2 = g_cand[row * 2 + 1];
    float inv = g_invn[row];
    float gap = g_gap[row];

    const float4* e4 = (const float4*)(emb + (size_t)row * D);
    float4 ev[4];
    #pragma unroll
    for (int q = 0; q < 4; ++q) ev[q] = e4[q * 32 + lane];

    int k = i1;
    if (gap < GAP_TAU) {
        const float4* p1 = (const float4*)(g_protoN + (size_t)i1 * D);
        const float4* p2 = (const float4*)(g_protoN + (size_t)i2 * D);
        float s1 = 0.f, s2 = 0.f;
        #pragma unroll
        for (int q = 0; q < 4; ++q) {
            float4 a = p1[q * 32 + lane];
            float4 b = p2[q * 32 + lane];
            s1 += ev[q].x * a.x + ev[q].y * a.y + ev[q].z * a.z + ev[q].w * a.w;
            s2 += ev[q].x * b.x + ev[q].y * b.y + ev[q].z * b.z + ev[q].w * b.w;
        }
        #pragma unroll
        for (int o = 16; o; o >>= 1) {
            s1 += __shfl_xor_sync(0xffffffffu, s1, o);
            s2 += __shfl_xor_sync(0xffffffffu, s2, o);
        }
        k = (s2 > s1 || (s2 == s1 && i2 < i1)) ? i2 : i1;
    }

    float4* dst = (float4*)(g_sums + (size_t)k * D);
    #pragma unroll
    for (int q = 0; q < 4; ++q) {
        float4 v = ev[q];
        v.x *= inv; v.y *= inv; v.z *= inv; v.w *= inv;
        atomicAdd(&dst[q * 32 + lane], v);
    }
    if (lane == 0) atomicAdd(&g_counts[k], 1);
}

// =====================================================================
// K1: normalize prototypes -> fp32 + fp16; zero sums/counts/flags
// =====================================================================
__global__ void k1_norm_proto(const float* __restrict__ protos) {
    int lane = threadIdx.x & 31;
    int row  = blockIdx.x * 8 + (threadIdx.x >> 5);
    int gt   = blockIdx.x * 256 + threadIdx.x;

    if (gt < KPROT) g_counts[gt] = 0;
    if (gt < NGRP)  g_flag[gt] = 0;
    if (gt < NGRP * 16 / 4) ((int*)g_done16)[gt] = 0;
    {
        float4* s4 = (float4*)g_sums;
        #pragma unroll
        for (int q = 0; q < 4; ++q) s4[q * 32768 + gt] = make_float4(0.f, 0.f, 0.f, 0.f);
    }

    const float4* src = (const float4*)(protos + (size_t)row * D);
    float4 v[4];
    float ss = 0.f;
    #pragma unroll
    for (int q = 0; q < 4; ++q) {
        v[q] = src[lane * 4 + q];
        ss += v[q].x * v[q].x + v[q].y * v[q].y + v[q].z * v[q].z + v[q].w * v[q].w;
    }
    #pragma unroll
    for (int o = 16; o; o >>= 1) ss += __shfl_xor_sync(0xffffffffu, ss, o);
    float inv = 1.f / fmaxf(sqrtf(ss), 1e-6f);

    float4* dstf = (float4*)(g_protoN + (size_t)row * D);
    uint32_t hb[8];
    #pragma unroll
    for (int q = 0; q < 4; ++q) {
        float4 w = make_float4(v[q].x * inv, v[q].y * inv, v[q].z * inv, v[q].w * inv);
        dstf[lane * 4 + q] = w;
        hb[q * 2 + 0] = f2_to_h2(w.x, w.y);
        hb[q * 2 + 1] = f2_to_h2(w.z, w.w);
    }
    uint4* dsth = (uint4*)(g_protoNh + (size_t)row * D + lane * 16);
    dsth[0] = make_uint4(hb[0], hb[1], hb[2], hb[3]);
    dsth[1] = make_uint4(hb[4], hb[5], hb[6], hb[7]);
}

// =====================================================================
// K2: fused normalize + fp16/f32acc mma GEMM + top-2 + gap certificate,
// PLUS cross-wave overlapped accumulation: CTA b consumes group b-148's
// k3 work interleaved into the MMA mainloop's second half (LSU work
// hides under tensor work). Producer release: threadfence + flag.
// =====================================================================
#define FOLD(slot, val, col) do { \
    float _v = (val); int _c = (col); \
    if (_v > tv1[slot]) { tv2[slot] = tv1[slot]; ti2[slot] = ti1[slot]; tv1[slot] = _v; ti1[slot] = _c; } \
    else if (_v > tv2[slot]) { tv2[slot] = _v; ti2[slot] = _c; } \
} while (0)

__global__ void __launch_bounds__(512, 1) k2_mma(const float* __restrict__ emb, int n) {
    extern __shared__ char smem[];
    const uint32_t sbA = smem_u32(smem);
    const uint32_t sbB = sbA + 131072;

    const int tid  = threadIdx.x;
    const int lane = tid & 31;
    const int wid  = tid >> 5;
    const int wm   = wid >> 2;
    const int wn   = wid & 3;
    const int row0 = blockIdx.x * 128;

    const int  jb     = (int)blockIdx.x - 148;   // group to consume
    const bool jvalid = (jb >= 0);
    bool doit = false;

    // ---- issue B stages 0,1 ----
    {
        const char* srcB0 = (const char*)g_protoNh;
        #pragma unroll
        for (int i = 0; i < 2; ++i) {
            int v = tid + i * 512;
            int pr = v >> 3, slot = v & 7;
            CP_ASYNC16(sbB + SWZ((uint32_t)(pr * 128 + slot * 16)),
                       srcB0 + (size_t)pr * 1024 + slot * 16);
        }
        CP_COMMIT();
        const char* srcB1 = (const char*)g_protoNh + 128;
        #pragma unroll
        for (int i = 0; i < 2; ++i) {
            int v = tid + i * 512;
            int pr = v >> 3, slot = v & 7;
            CP_ASYNC16(sbB + 16384u + SWZ((uint32_t)(pr * 128 + slot * 16)),
                       srcB1 + (size_t)pr * 1024 + slot * 16);
        }
        CP_COMMIT();
    }

    // ---- A phase ----
    #pragma unroll 1
    for (int rr = 0; rr < 8; ++rr) {
        int r = wid * 8 + rr;
        int grow = row0 + r;
        const float4* src = (const float4*)(emb + (size_t)grow * D);
        float4 v[4];
        float ss = 0.f;
        if (grow < n) {
            #pragma unroll
            for (int q = 0; q < 4; ++q) {
                v[q] = src[lane * 4 + q];
                ss += v[q].x * v[q].x + v[q].y * v[q].y + v[q].z * v[q].z + v[q].w * v[q].w;
            }
        } else {
            #pragma unroll
            for (int q = 0; q < 4; ++q) v[q] = make_float4(0.f, 0.f, 0.f, 0.f);
        }
        #pragma unroll
        for (int o = 16; o; o >>= 1) ss += __shfl_xor_sync(0xffffffffu, ss, o);
        float inv = 1.f / fmaxf(sqrtf(ss), 1e-6f);
        if (lane == 0 && grow < n) g_invn[grow] = inv;

        uint32_t hb[8];
        #pragma unroll
        for (int q = 0; q < 4; ++q) {
            hb[q * 2 + 0] = f2_to_h2(v[q].x * inv, v[q].y * inv);
            hb[q * 2 + 1] = f2_to_h2(v[q].z * inv, v[q].w * inv);
        }
        #pragma unroll
        for (int h = 0; h < 2; ++h) {
            int s = lane * 2 + h;
            uint32_t off = (uint32_t)(s >> 3) * 16384u + SWZ((uint32_t)(r * 128 + (s & 7) * 16));
            *(uint4*)(smem + off) = make_uint4(hb[h * 4 + 0], hb[h * 4 + 1], hb[h * 4 + 2], hb[h * 4 + 3]);
        }
    }

    float acc[2][4][4];
    float tv1[4], tv2[4];
    int   ti1[4], ti2[4];
    #pragma unroll
    for (int s = 0; s < 4; ++s) { tv1[s] = -3.4e38f; tv2[s] = -3.4e38f; ti1[s] = 0; ti2[s] = 0; }

    uint32_t rbA[2], xA[2], rbB[2], xB[2];
    {
        #pragma unroll
        for (int mf = 0; mf < 2; ++mf) {
            uint32_t rb = (uint32_t)((wm * 32 + mf * 16 + (lane & 15)) * 128 + (lane >> 4) * 16);
            rbA[mf] = rb; xA[mf] = (rb >> 3) & 0x70;
        }
        #pragma unroll
        for (int nh = 0; nh < 2; ++nh) {
            uint32_t rw = (uint32_t)(wn * 32 + nh * 16 + ((lane >> 4) << 3) + (lane & 7));
            uint32_t rb = rw * 128 + (((uint32_t)lane >> 3) & 1u) * 16u;
            rbB[nh] = rb; xB[nh] = (rb >> 3) & 0x70;
        }
    }

    __syncthreads();

    for (int idx = 0; idx < 64; ++idx) {
        const int kc = idx & 7;

        if (idx + 2 < 64) {
            const int nxt = idx + 2;
            const int pt2 = nxt >> 3, kc2 = nxt & 7;
            const char* srcB = (const char*)(g_protoNh + (size_t)(pt2 * 128) * D + kc2 * 64);
            uint32_t base = sbB + (uint32_t)(nxt & 3) * 16384u;
            #pragma unroll
            for (int i = 0; i < 2; ++i) {
                int v = tid + i * 512;
                int pr = v >> 3, slot = v & 7;
                CP_ASYNC16(base + SWZ((uint32_t)(pr * 128 + slot * 16)),
                           srcB + (size_t)pr * 1024 + slot * 16);
            }
            CP_COMMIT();
            CP_WAIT(2);
        } else {
            CP_WAIT(0);
        }
        __syncthreads();

        if (kc == 0) {
            #pragma unroll
            for (int mf = 0; mf < 2; ++mf)
                #pragma unroll
                for (int nf = 0; nf < 4; ++nf)
                    #pragma unroll
                    for (int q = 0; q < 4; ++q) acc[mf][nf][q] = 0.f;
        }

        const uint32_t aBase = sbA + (uint32_t)kc * 16384u;
        const uint32_t bBase = sbB + (uint32_t)(idx & 3) * 16384u;
        #pragma unroll
        for (int ks = 0; ks < 4; ++ks) {
            uint32_t af[2][4], bf[2][4];
            #pragma unroll
            for (int mf = 0; mf < 2; ++mf)
                ldsm_x4(af[mf], aBase + ((rbA[mf] + ks * 32) ^ xA[mf]));
            #pragma unroll
            for (int nh = 0; nh < 2; ++nh)
                ldsm_x4(bf[nh], bBase + ((rbB[nh] + ks * 32) ^ xB[nh]));
            #pragma unroll
            for (int mf = 0; mf < 2; ++mf) {
                #pragma unroll
                for (int nh = 0; nh < 2; ++nh) {
                    mma_f16f32(acc[mf][nh * 2 + 0], af[mf], bf[nh][0], bf[nh][1]);
                    mma_f16f32(acc[mf][nh * 2 + 1], af[mf], bf[nh][2], bf[nh][3]);
                }
            }
        }

        if (kc == 7) {
            const int pt = idx >> 3;
            #pragma unroll
            for (int mf = 0; mf < 2; ++mf) {
                #pragma unroll
                for (int nf = 0; nf < 4; ++nf) {
                    int col = pt * 128 + wn * 32 + nf * 8 + (lane & 3) * 2;
                    FOLD(mf * 2 + 0, acc[mf][nf][0], col);
                    FOLD(mf * 2 + 0, acc[mf][nf][1], col + 1);
                    FOLD(mf * 2 + 1, acc[mf][nf][2], col);
                    FOLD(mf * 2 + 1, acc[mf][nf][3], col + 1);
                }
            }
        }

        // ---- overlapped consumption of group jb (one row/warp per 4 iters) ----
        if (jvalid && idx >= 35 && (idx & 3) == 3) {
            if (idx == 35) {
                int f = 0;
                if (lane == 0) f = atomicAdd(&g_flag[jb], 0);
                f = __shfl_sync(0xffffffffu, f, 0);
                if (f) {
                    doit = true;
                    __threadfence();   // acquire: order subsequent reads after flag
                    if (lane == 0) g_done16[jb * 16 + wid] = 1;
                }
            }
            if (doit) {
                int slot = (idx - 35) >> 2;        // 0..7
                int row = jb * 128 + wid * 8 + slot;
                if (row < n) accum_row(emb, row, lane);
            }
        }
    }

    // ---- quad reduce + cross-warp merge (top-2) ----
    #pragma unroll
    for (int s = 0; s < 4; ++s) {
        #pragma unroll
        for (int off = 1; off <= 2; off <<= 1) {
            float ov1 = __shfl_xor_sync(0xffffffffu, tv1[s], off);
            int   oi1 = __shfl_xor_sync(0xffffffffu, ti1[s], off);
            float ov2 = __shfl_xor_sync(0xffffffffu, tv2[s], off);
            int   oi2 = __shfl_xor_sync(0xffffffffu, ti2[s], off);
            bool alead = (tv1[s] > ov1) || (tv1[s] == ov1 && ti1[s] < oi1);
            float nv1 = alead ? tv1[s] : ov1;  int ni1 = alead ? ti1[s] : oi1;
            float cv  = alead ? ov1 : tv1[s];  int ci  = alead ? oi1 : ti1[s];
            float sv  = alead ? tv2[s] : ov2;  int si  = alead ? ti2[s] : oi2;
            bool slead = (sv > cv) || (sv == cv && si < ci);
            tv1[s] = nv1; ti1[s] = ni1;
            tv2[s] = slead ? sv : cv; ti2[s] = slead ? si : ci;
        }
    }
    __syncthreads();

    float4* buf = (float4*)(smem + 131072);
    if ((lane & 3) == 0) {
        #pragma unroll
        for (int s = 0; s < 4; ++s) {
            int r = wm * 32 + (s >> 1) * 16 + (lane >> 2) + (s & 1) * 8;
            buf[wn * 128 + r] = make_float4(tv1[s], __int_as_float(ti1[s]),
                                            tv2[s], __int_as_float(ti2[s]));
        }
    }
    __syncthreads();

    if (tid < 128) {
        float4 m = buf[tid];
        float v1 = m.x; int i1 = __float_as_int(m.y);
        float v2 = m.z; int i2 = __float_as_int(m.w);
        #pragma unroll
        for (int w = 1; w < 4; ++w) {
            float4 o = buf[w * 128 + tid];
            float ov1 = o.x; int oi1 = __float_as_int(o.y);
            float ov2 = o.z; int oi2 = __float_as_int(o.w);
            bool alead = (v1 > ov1) || (v1 == ov1 && i1 < oi1);
            float nv1 = alead ? v1 : ov1;  int ni1 = alead ? i1 : oi1;
            float cv  = alead ? ov1 : v1;  int ci  = alead ? oi1 : i1;
            float sv  = alead ? v2 : ov2;  int si  = alead ? i2 : oi2;
            bool slead = (sv > cv) || (sv == cv && si < ci);
            v1 = nv1; i1 = ni1;
            v2 = slead ? sv : cv; i2 = slead ? si : ci;
        }
        int grow = row0 + tid;
        if (grow < n) {
            g_cand[grow * 2 + 0] = i1;
            g_cand[grow * 2 + 1] = i2;
            g_gap[grow] = v1 - v2;
        }
    }

    // ---- release: publish this group's candidates ----
    __syncthreads();
    if (tid == 0) {
        __threadfence();
        atomicExch(&g_flag[blockIdx.x], 1);
    }
}

// =====================================================================
// K3 cleanup: process groups/warp-chunks not consumed inside k2.
// grid = NGRP x 512; warp w of block j handles rows j*128+w*8 .. +7.
// =====================================================================
__global__ void k3_cleanup(const float* __restrict__ emb, int n) {
    int j    = blockIdx.x;
    int lane = threadIdx.x & 31;
    int wid  = threadIdx.x >> 5;

    if (g_done16[j * 16 + wid]) return;
    #pragma unroll 1
    for (int slot = 0; slot < 8; ++slot) {
        int row = j * 128 + wid * 8 + slot;
        if (row < n) accum_row(emb, row, lane);
    }
}

// =====================================================================
// K4: EMA + renormalize + where(has). Block (128 thr) per prototype row.
// =====================================================================
__global__ void k4_final(const float* __restrict__ protos, float* __restrict__ out) {
    __shared__ float red[4];
    int k   = blockIdx.x;
    int t   = threadIdx.x;
    int lane = t & 31, w = t >> 5;

    int   cnt = g_counts[k];
    float cf  = fmaxf((float)cnt, 1.f);

    float4 pv = *(const float4*)(protos + (size_t)k * D + t * 4);
    float4 sm = *(const float4*)(g_sums + (size_t)k * D + t * 4);
    float4 uv = make_float4(0.9f * pv.x + 0.1f * (sm.x / cf),
                            0.9f * pv.y + 0.1f * (sm.y / cf),
                            0.9f * pv.z + 0.1f * (sm.z / cf),
                            0.9f * pv.w + 0.1f * (sm.w / cf));
    float ss = uv.x * uv.x + uv.y * uv.y + uv.z * uv.z + uv.w * uv.w;
    #pragma unroll
    for (int o = 16; o; o >>= 1) ss += __shfl_xor_sync(0xffffffffu, ss, o);
    if (lane == 0) red[w] = ss;
    __syncthreads();
    ss = red[0] + red[1] + red[2] + red[3];
    float inv = 1.f / fmaxf(sqrtf(ss), 1e-6f);

    float4 o4 = (cnt > 0)
        ? make_float4(uv.x * inv, uv.y * inv, uv.z * inv, uv.w * inv)
        : pv;
    *(float4*)(out + (size_t)k * D + t * 4) = o4;
}

// =====================================================================
extern "C" void kernel_launch(void* const* d_in, const int* in_sizes, int n_in,
                              void* d_out, int out_size) {
    const float* emb    = (const float*)d_in[0];
    const float* protos = (const float*)d_in[1];
    float* out = (float*)d_out;
    int n = in_sizes[0] / D;   // 131072
    int ngrp = (n + 127) / 128;

    const int smem2 = 131072 + 4 * 16384;  // 192 KB
    cudaFuncSetAttribute(k2_mma, cudaFuncAttributeMaxDynamicSharedMemorySize, smem2);

    k1_norm_proto<<<KPROT / 8, 256>>>(protos);
    k2_mma<<<ngrp, 512, smem2>>>(emb, n);
    k3_cleanup<<<ngrp, 512>>>(emb, n);
    k4_final<<<KPROT, 128>>>(protos, out);
}

// round 13
// speedup vs baseline: 1.0363x; 1.0363x over previous
#include <cuda_runtime.h>
#include <cuda_fp16.h>
#include <cstdint>

#define D      512
#define KPROT  1024
#define NMAX   131072
#define MAXC   1024
#define GAP_TAU 5e-4f

// ---------------- device scratch ----------------
__device__ float  g_protoN [KPROT * D];   // normalized prototypes fp32 (rescoring)
__device__ __half g_protoNh[KPROT * D];   // normalized prototypes fp16 (GEMM)
__device__ float  g_sums   [KPROT * D];   // overflow-fallback sums (normally all zero)
__device__ int    g_cnt    [KPROT];
__device__ float  g_invn   [NMAX];
__device__ float  g_gap    [NMAX];
__device__ int    g_cand   [NMAX * 2];
__device__ int    g_rows   [KPROT * MAXC]; // per-cluster row buckets

// ---------------- helpers ----------------
__device__ __forceinline__ uint32_t smem_u32(const void* p) {
    uint32_t a;
    asm("{ .reg .u64 t; cvta.to.shared.u64 t, %1; cvt.u32.u64 %0, t; }" : "=r"(a) : "l"(p));
    return a;
}
#define SWZ(x) ((x) ^ (((x) >> 3) & 0x70))

#define CP_ASYNC16(dst, src) \
    asm volatile("cp.async.cg.shared.global [%0], [%1], 16;" :: "r"(dst), "l"(src))
#define CP_COMMIT() asm volatile("cp.async.commit_group;")
#define CP_WAIT(n)  asm volatile("cp.async.wait_group %0;" :: "n"(n))

__device__ __forceinline__ void ldsm_x4(uint32_t a[4], uint32_t addr) {
    asm volatile("ldmatrix.sync.aligned.m8n8.x4.shared.b16 {%0,%1,%2,%3}, [%4];"
        : "=r"(a[0]), "=r"(a[1]), "=r"(a[2]), "=r"(a[3]) : "r"(addr));
}
__device__ __forceinline__ void mma_f16f32(float c[4], const uint32_t a[4], uint32_t b0, uint32_t b1) {
    asm volatile(
        "mma.sync.aligned.m16n8k16.row.col.f32.f16.f16.f32 "
        "{%0,%1,%2,%3},{%4,%5,%6,%7},{%8,%9},{%0,%1,%2,%3};"
        : "+f"(c[0]), "+f"(c[1]), "+f"(c[2]), "+f"(c[3])
        : "r"(a[0]), "r"(a[1]), "r"(a[2]), "r"(a[3]), "r"(b0), "r"(b1));
}
__device__ __forceinline__ uint32_t f2_to_h2(float x, float y) {
    __half2 h = __float22half2_rn(make_float2(x, y));
    return *(uint32_t*)&h;
}

// =====================================================================
// K1: normalize prototypes -> fp32 + fp16; zero counters + fallback sums
// =====================================================================
__global__ void k1_norm_proto(const float* __restrict__ protos) {
    int lane = threadIdx.x & 31;
    int row  = blockIdx.x * 8 + (threadIdx.x >> 5);
    int gt   = blockIdx.x * 256 + threadIdx.x;

    if (gt < KPROT) g_cnt[gt] = 0;
    {
        float4* s4 = (float4*)g_sums;
        #pragma unroll
        for (int q = 0; q < 4; ++q) s4[q * 32768 + gt] = make_float4(0.f, 0.f, 0.f, 0.f);
    }

    const float4* src = (const float4*)(protos + (size_t)row * D);
    float4 v[4];
    float ss = 0.f;
    #pragma unroll
    for (int q = 0; q < 4; ++q) {
        v[q] = src[lane * 4 + q];
        ss += v[q].x * v[q].x + v[q].y * v[q].y + v[q].z * v[q].z + v[q].w * v[q].w;
    }
    #pragma unroll
    for (int o = 16; o; o >>= 1) ss += __shfl_xor_sync(0xffffffffu, ss, o);
    float inv = 1.f / fmaxf(sqrtf(ss), 1e-6f);

    float4* dstf = (float4*)(g_protoN + (size_t)row * D);
    uint32_t hb[8];
    #pragma unroll
    for (int q = 0; q < 4; ++q) {
        float4 w = make_float4(v[q].x * inv, v[q].y * inv, v[q].z * inv, v[q].w * inv);
        dstf[lane * 4 + q] = w;
        hb[q * 2 + 0] = f2_to_h2(w.x, w.y);
        hb[q * 2 + 1] = f2_to_h2(w.z, w.w);
    }
    uint4* dsth = (uint4*)(g_protoNh + (size_t)row * D + lane * 16);
    dsth[0] = make_uint4(hb[0], hb[1], hb[2], hb[3]);
    dsth[1] = make_uint4(hb[4], hb[5], hb[6], hb[7]);
}

// =====================================================================
// K2: fused normalize + fp16/f32acc mma GEMM [128x1024x512] per CTA
// + per-row top-2 candidates + gap certificate. (R11 version, unchanged)
// =====================================================================
#define FOLD(slot, val, col) do { \
    float _v = (val); int _c = (col); \
    if (_v > tv1[slot]) { tv2[slot] = tv1[slot]; ti2[slot] = ti1[slot]; tv1[slot] = _v; ti1[slot] = _c; } \
    else if (_v > tv2[slot]) { tv2[slot] = _v; ti2[slot] = _c; } \
} while (0)

__global__ void __launch_bounds__(512, 1) k2_mma(const float* __restrict__ emb, int n) {
    extern __shared__ char smem[];
    const uint32_t sbA = smem_u32(smem);
    const uint32_t sbB = sbA + 131072;

    const int tid  = threadIdx.x;
    const int lane = tid & 31;
    const int wid  = tid >> 5;
    const int wm   = wid >> 2;
    const int wn   = wid & 3;
    const int row0 = blockIdx.x * 128;

    // ---- issue B stages 0,1 ----
    {
        const char* srcB0 = (const char*)g_protoNh;
        #pragma unroll
        for (int i = 0; i < 2; ++i) {
            int v = tid + i * 512;
            int pr = v >> 3, slot = v & 7;
            CP_ASYNC16(sbB + SWZ((uint32_t)(pr * 128 + slot * 16)),
                       srcB0 + (size_t)pr * 1024 + slot * 16);
        }
        CP_COMMIT();
        const char* srcB1 = (const char*)g_protoNh + 128;
        #pragma unroll
        for (int i = 0; i < 2; ++i) {
            int v = tid + i * 512;
            int pr = v >> 3, slot = v & 7;
            CP_ASYNC16(sbB + 16384u + SWZ((uint32_t)(pr * 128 + slot * 16)),
                       srcB1 + (size_t)pr * 1024 + slot * 16);
        }
        CP_COMMIT();
    }

    // ---- A phase ----
    #pragma unroll 1
    for (int rr = 0; rr < 8; ++rr) {
        int r = wid * 8 + rr;
        int grow = row0 + r;
        const float4* src = (const float4*)(emb + (size_t)grow * D);
        float4 v[4];
        float ss = 0.f;
        if (grow < n) {
            #pragma unroll
            for (int q = 0; q < 4; ++q) {
                v[q] = src[lane * 4 + q];
                ss += v[q].x * v[q].x + v[q].y * v[q].y + v[q].z * v[q].z + v[q].w * v[q].w;
            }
        } else {
            #pragma unroll
            for (int q = 0; q < 4; ++q) v[q] = make_float4(0.f, 0.f, 0.f, 0.f);
        }
        #pragma unroll
        for (int o = 16; o; o >>= 1) ss += __shfl_xor_sync(0xffffffffu, ss, o);
        float inv = 1.f / fmaxf(sqrtf(ss), 1e-6f);
        if (lane == 0 && grow < n) g_invn[grow] = inv;

        uint32_t hb[8];
        #pragma unroll
        for (int q = 0; q < 4; ++q) {
            hb[q * 2 + 0] = f2_to_h2(v[q].x * inv, v[q].y * inv);
            hb[q * 2 + 1] = f2_to_h2(v[q].z * inv, v[q].w * inv);
        }
        #pragma unroll
        for (int h = 0; h < 2; ++h) {
            int s = lane * 2 + h;
            uint32_t off = (uint32_t)(s >> 3) * 16384u + SWZ((uint32_t)(r * 128 + (s & 7) * 16));
            *(uint4*)(smem + off) = make_uint4(hb[h * 4 + 0], hb[h * 4 + 1], hb[h * 4 + 2], hb[h * 4 + 3]);
        }
    }

    float acc[2][4][4];
    float tv1[4], tv2[4];
    int   ti1[4], ti2[4];
    #pragma unroll
    for (int s = 0; s < 4; ++s) { tv1[s] = -3.4e38f; tv2[s] = -3.4e38f; ti1[s] = 0; ti2[s] = 0; }

    uint32_t rbA[2], xA[2], rbB[2], xB[2];
    {
        #pragma unroll
        for (int mf = 0; mf < 2; ++mf) {
            uint32_t rb = (uint32_t)((wm * 32 + mf * 16 + (lane & 15)) * 128 + (lane >> 4) * 16);
            rbA[mf] = rb; xA[mf] = (rb >> 3) & 0x70;
        }
        #pragma unroll
        for (int nh = 0; nh < 2; ++nh) {
            uint32_t rw = (uint32_t)(wn * 32 + nh * 16 + ((lane >> 4) << 3) + (lane & 7));
            uint32_t rb = rw * 128 + (((uint32_t)lane >> 3) & 1u) * 16u;
            rbB[nh] = rb; xB[nh] = (rb >> 3) & 0x70;
        }
    }

    __syncthreads();

    for (int idx = 0; idx < 64; ++idx) {
        const int kc = idx & 7;

        if (idx + 2 < 64) {
            const int nxt = idx + 2;
            const int pt2 = nxt >> 3, kc2 = nxt & 7;
            const char* srcB = (const char*)(g_protoNh + (size_t)(pt2 * 128) * D + kc2 * 64);
            uint32_t base = sbB + (uint32_t)(nxt & 3) * 16384u;
            #pragma unroll
            for (int i = 0; i < 2; ++i) {
                int v = tid + i * 512;
                int pr = v >> 3, slot = v & 7;
                CP_ASYNC16(base + SWZ((uint32_t)(pr * 128 + slot * 16)),
                           srcB + (size_t)pr * 1024 + slot * 16);
            }
            CP_COMMIT();
            CP_WAIT(2);
        } else {
            CP_WAIT(0);
        }
        __syncthreads();

        if (kc == 0) {
            #pragma unroll
            for (int mf = 0; mf < 2; ++mf)
                #pragma unroll
                for (int nf = 0; nf < 4; ++nf)
                    #pragma unroll
                    for (int q = 0; q < 4; ++q) acc[mf][nf][q] = 0.f;
        }

        const uint32_t aBase = sbA + (uint32_t)kc * 16384u;
        const uint32_t bBase = sbB + (uint32_t)(idx & 3) * 16384u;
        #pragma unroll
        for (int ks = 0; ks < 4; ++ks) {
            uint32_t af[2][4], bf[2][4];
            #pragma unroll
            for (int mf = 0; mf < 2; ++mf)
                ldsm_x4(af[mf], aBase + ((rbA[mf] + ks * 32) ^ xA[mf]));
            #pragma unroll
            for (int nh = 0; nh < 2; ++nh)
                ldsm_x4(bf[nh], bBase + ((rbB[nh] + ks * 32) ^ xB[nh]));
            #pragma unroll
            for (int mf = 0; mf < 2; ++mf) {
                #pragma unroll
                for (int nh = 0; nh < 2; ++nh) {
                    mma_f16f32(acc[mf][nh * 2 + 0], af[mf], bf[nh][0], bf[nh][1]);
                    mma_f16f32(acc[mf][nh * 2 + 1], af[mf], bf[nh][2], bf[nh][3]);
                }
            }
        }

        if (kc == 7) {
            const int pt = idx >> 3;
            #pragma unroll
            for (int mf = 0; mf < 2; ++mf) {
                #pragma unroll
                for (int nf = 0; nf < 4; ++nf) {
                    int col = pt * 128 + wn * 32 + nf * 8 + (lane & 3) * 2;
                    FOLD(mf * 2 + 0, acc[mf][nf][0], col);
                    FOLD(mf * 2 + 0, acc[mf][nf][1], col + 1);
                    FOLD(mf * 2 + 1, acc[mf][nf][2], col);
                    FOLD(mf * 2 + 1, acc[mf][nf][3], col + 1);
                }
            }
        }
    }

    // ---- quad reduce + cross-warp merge (top-2) ----
    #pragma unroll
    for (int s = 0; s < 4; ++s) {
        #pragma unroll
        for (int off = 1; off <= 2; off <<= 1) {
            float ov1 = __shfl_xor_sync(0xffffffffu, tv1[s], off);
            int   oi1 = __shfl_xor_sync(0xffffffffu, ti1[s], off);
            float ov2 = __shfl_xor_sync(0xffffffffu, tv2[s], off);
            int   oi2 = __shfl_xor_sync(0xffffffffu, ti2[s], off);
            bool alead = (tv1[s] > ov1) || (tv1[s] == ov1 && ti1[s] < oi1);
            float nv1 = alead ? tv1[s] : ov1;  int ni1 = alead ? ti1[s] : oi1;
            float cv  = alead ? ov1 : tv1[s];  int ci  = alead ? oi1 : ti1[s];
            float sv  = alead ? tv2[s] : ov2;  int si  = alead ? ti2[s] : oi2;
            bool slead = (sv > cv) || (sv == cv && si < ci);
            tv1[s] = nv1; ti1[s] = ni1;
            tv2[s] = slead ? sv : cv; ti2[s] = slead ? si : ci;
        }
    }
    __syncthreads();

    float4* buf = (float4*)(smem + 131072);
    if ((lane & 3) == 0) {
        #pragma unroll
        for (int s = 0; s < 4; ++s) {
            int r = wm * 32 + (s >> 1) * 16 + (lane >> 2) + (s & 1) * 8;
            buf[wn * 128 + r] = make_float4(tv1[s], __int_as_float(ti1[s]),
                                            tv2[s], __int_as_float(ti2[s]));
        }
    }
    __syncthreads();

    if (tid < 128) {
        float4 m = buf[tid];
        float v1 = m.x; int i1 = __float_as_int(m.y);
        float v2 = m.z; int i2 = __float_as_int(m.w);
        #pragma unroll
        for (int w = 1; w < 4; ++w) {
            float4 o = buf[w * 128 + tid];
            float ov1 = o.x; int oi1 = __float_as_int(o.y);
            float ov2 = o.z; int oi2 = __float_as_int(o.w);
            bool alead = (v1 > ov1) || (v1 == ov1 && i1 < oi1);
            float nv1 = alead ? v1 : ov1;  int ni1 = alead ? i1 : oi1;
            float cv  = alead ? ov1 : v1;  int ci  = alead ? oi1 : i1;
            float sv  = alead ? v2 : ov2;  int si  = alead ? i2 : oi2;
            bool slead = (sv > cv) || (sv == cv && si < ci);
            v1 = nv1; i1 = ni1;
            v2 = slead ? sv : cv; i2 = slead ? si : ci;
        }
        int grow = row0 + tid;
        if (grow < n) {
            g_cand[grow * 2 + 0] = i1;
            g_cand[grow * 2 + 1] = i2;
            g_gap[grow] = v1 - v2;
        }
    }
}

// =====================================================================
// K3: assignment + bucket build. Thread per row; uncertain rows
// (gap < tau, ~4%) rescored warp-cooperatively via ballot loop.
// One small int atomic per row (bucket counters).
// =====================================================================
__global__ void k3_assign(const float* __restrict__ emb, int n) {
    int tid  = threadIdx.x;
    int lane = tid & 31;
    int row  = blockIdx.x * 256 + tid;
    bool valid = row < n;

    int i1 = 0, i2 = 0;
    float gap = 1e30f;
    if (valid) {
        i1  = g_cand[row * 2 + 0];
        i2  = g_cand[row * 2 + 1];
        gap = g_gap[row];
    }
    int k = i1;

    unsigned mask = __ballot_sync(0xffffffffu, valid && gap < GAP_TAU);
    while (mask) {
        int src = __ffs(mask) - 1;
        mask &= mask - 1;
        int rrow = __shfl_sync(0xffffffffu, row, src);
        int ri1  = __shfl_sync(0xffffffffu, i1, src);
        int ri2  = __shfl_sync(0xffffffffu, i2, src);

        const float4* e4 = (const float4*)(emb + (size_t)rrow * D);
        const float4* p1 = (const float4*)(g_protoN + (size_t)ri1 * D);
        const float4* p2 = (const float4*)(g_protoN + (size_t)ri2 * D);
        float s1 = 0.f, s2 = 0.f;
        #pragma unroll
        for (int q = 0; q < 4; ++q) {
            float4 e = e4[q * 32 + lane];
            float4 a = p1[q * 32 + lane];
            float4 b = p2[q * 32 + lane];
            s1 += e.x * a.x + e.y * a.y + e.z * a.z + e.w * a.w;
            s2 += e.x * b.x + e.y * b.y + e.z * b.z + e.w * b.w;
        }
        #pragma unroll
        for (int o = 16; o; o >>= 1) {
            s1 += __shfl_xor_sync(0xffffffffu, s1, o);
            s2 += __shfl_xor_sync(0xffffffffu, s2, o);
        }
        int rk = (s2 > s1 || (s2 == s1 && ri2 < ri1)) ? ri2 : ri1;
        if (lane == src) k = rk;
    }

    if (valid) {
        int pos = atomicAdd(&g_cnt[k], 1);
        if (pos < MAXC) {
            g_rows[k * MAXC + pos] = row;
        } else {
            // overflow fallback (probability ~0): direct atomic accumulation
            float inv = g_invn[row];
            for (int d = 0; d < D; ++d)
                atomicAdd(&g_sums[(size_t)k * D + d], emb[(size_t)row * D + d] * inv);
        }
    }
}

// =====================================================================
// K4: gather-reduce + EMA + renormalize. Block (128 thr) per cluster.
// Streams this cluster's rows from emb (coalesced, no atomics).
// =====================================================================
__global__ void k4_final(const float* __restrict__ protos,
                         const float* __restrict__ emb,
                         float* __restrict__ out) {
    __shared__ float red[4];
    __shared__ int   rows_s[MAXC > 2048 ? MAXC : 2048];  // row indices (MAXC=1024 fits)
    int k    = blockIdx.x;
    int t    = threadIdx.x;        // 0..127, owns floats [4t, 4t+4)
    int lane = t & 31, w = t >> 5;

    int cnt = g_cnt[k];
    int m   = cnt < MAXC ? cnt : MAXC;

    // stage row list into smem (also preloads invn access pattern)
    for (int i = t; i < m; i += 128) rows_s[i] = g_rows[k * MAXC + i];
    __syncthreads();

    // overflow-fallback partial sums (normally zero)
    float4 acc = *(const float4*)(g_sums + (size_t)k * D + t * 4);

    #pragma unroll 1
    for (int i = 0; i < m; ++i) {
        int r = rows_s[i];
        float inv = g_invn[r];
        float4 v = *(const float4*)(emb + (size_t)r * D + t * 4);
        acc.x += v.x * inv; acc.y += v.y * inv;
        acc.z += v.z * inv; acc.w += v.w * inv;
    }

    float cf = fmaxf((float)cnt, 1.f);
    float4 pv = *(const float4*)(protos + (size_t)k * D + t * 4);
    float4 uv = make_float4(0.9f * pv.x + 0.1f * (acc.x / cf),
                            0.9f * pv.y + 0.1f * (acc.y / cf),
                            0.9f * pv.z + 0.1f * (acc.z / cf),
                            0.9f * pv.w + 0.1f * (acc.w / cf));
    float ss = uv.x * uv.x + uv.y * uv.y + uv.z * uv.z + uv.w * uv.w;
    #pragma unroll
    for (int o = 16; o; o >>= 1) ss += __shfl_xor_sync(0xffffffffu, ss, o);
    if (lane == 0) red[w] = ss;
    __syncthreads();
    ss = red[0] + red[1] + red[2] + red[3];
    float inv = 1.f / fmaxf(sqrtf(ss), 1e-6f);

    float4 o4 = (cnt > 0)
        ? make_float4(uv.x * inv, uv.y * inv, uv.z * inv, uv.w * inv)
        : pv;
    *(float4*)(out + (size_t)k * D + t * 4) = o4;
}

// =====================================================================
extern "C" void kernel_launch(void* const* d_in, const int* in_sizes, int n_in,
                              void* d_out, int out_size) {
    const float* emb    = (const float*)d_in[0];
    const float* protos = (const float*)d_in[1];
    float* out = (float*)d_out;
    int n = in_sizes[0] / D;   // 131072
    int ngrp = (n + 127) / 128;

    const int smem2 = 131072 + 4 * 16384;  // 192 KB
    cudaFuncSetAttribute(k2_mma, cudaFuncAttributeMaxDynamicSharedMemorySize, smem2);

    k1_norm_proto<<<KPROT / 8, 256>>>(protos);
    k2_mma<<<ngrp, 512, smem2>>>(emb, n);
    k3_assign<<<(n + 255) / 256, 256>>>(emb, n);
    k4_final<<<KPROT, 128>>>(protos, emb, out);
}

// round 14
// speedup vs baseline: 1.1262x; 1.0868x over previous
#include <cuda_runtime.h>
#include <cuda_fp16.h>
#include <cstdint>

#define D      512
#define KPROT  1024
#define NMAX   131072
#define GAP_TAU 5e-4f   // applied to gap_raw * invnorm (normalized units)

// ---------------- device scratch ----------------
__device__ float  g_protoN [KPROT * D];   // normalized prototypes fp32 (rescoring)
__device__ __half g_protoNh[KPROT * D];   // normalized prototypes fp16 (GEMM)
__device__ float  g_sums   [KPROT * D];
__device__ int    g_counts [KPROT];
__device__ float  g_gap    [NMAX];        // raw-unit top1-top2 gap from fp16 GEMM
__device__ int    g_cand   [NMAX * 2];    // top-2 candidate protos per row

// ---------------- helpers ----------------
__device__ __forceinline__ uint32_t smem_u32(const void* p) {
    uint32_t a;
    asm("{ .reg .u64 t; cvta.to.shared.u64 t, %1; cvt.u32.u64 %0, t; }" : "=r"(a) : "l"(p));
    return a;
}
#define SWZ(x) ((x) ^ (((x) >> 3) & 0x70))

#define CP_ASYNC16(dst, src) \
    asm volatile("cp.async.cg.shared.global [%0], [%1], 16;" :: "r"(dst), "l"(src))
#define CP_COMMIT() asm volatile("cp.async.commit_group;")
#define CP_WAIT(n)  asm volatile("cp.async.wait_group %0;" :: "n"(n))

__device__ __forceinline__ void ldsm_x4(uint32_t a[4], uint32_t addr) {
    asm volatile("ldmatrix.sync.aligned.m8n8.x4.shared.b16 {%0,%1,%2,%3}, [%4];"
        : "=r"(a[0]), "=r"(a[1]), "=r"(a[2]), "=r"(a[3]) : "r"(addr));
}
// fp16 inputs, f32 accumulate
__device__ __forceinline__ void mma_f16f32(float c[4], const uint32_t a[4], uint32_t b0, uint32_t b1) {
    asm volatile(
        "mma.sync.aligned.m16n8k16.row.col.f32.f16.f16.f32 "
        "{%0,%1,%2,%3},{%4,%5,%6,%7},{%8,%9},{%0,%1,%2,%3};"
        : "+f"(c[0]), "+f"(c[1]), "+f"(c[2]), "+f"(c[3])
        : "r"(a[0]), "r"(a[1]), "r"(a[2]), "r"(a[3]), "r"(b0), "r"(b1));
}
__device__ __forceinline__ uint32_t f2_to_h2(float x, float y) {
    __half2 h = __float22half2_rn(make_float2(x, y));
    return *(uint32_t*)&h;
}

// =====================================================================
// K1: normalize prototypes -> fp32 + fp16; zero sums/counts
// =====================================================================
__global__ void k1_norm_proto(const float* __restrict__ protos) {
    int lane = threadIdx.x & 31;
    int row  = blockIdx.x * 8 + (threadIdx.x >> 5);

    if (blockIdx.x < 4) g_counts[blockIdx.x * 256 + threadIdx.x] = 0;
    {
        float4* s4 = (float4*)g_sums;
        int t = blockIdx.x * 256 + threadIdx.x;
        #pragma unroll
        for (int q = 0; q < 4; ++q) s4[q * 32768 + t] = make_float4(0.f, 0.f, 0.f, 0.f);
    }

    const float4* src = (const float4*)(protos + (size_t)row * D);
    float4 v[4];
    float ss = 0.f;
    #pragma unroll
    for (int q = 0; q < 4; ++q) {
        v[q] = src[lane * 4 + q];
        ss += v[q].x * v[q].x + v[q].y * v[q].y + v[q].z * v[q].z + v[q].w * v[q].w;
    }
    #pragma unroll
    for (int o = 16; o; o >>= 1) ss += __shfl_xor_sync(0xffffffffu, ss, o);
    float inv = 1.f / fmaxf(sqrtf(ss), 1e-6f);

    float4* dstf = (float4*)(g_protoN + (size_t)row * D);
    uint32_t hb[8];
    #pragma unroll
    for (int q = 0; q < 4; ++q) {
        float4 w = make_float4(v[q].x * inv, v[q].y * inv, v[q].z * inv, v[q].w * inv);
        dstf[lane * 4 + q] = w;
        hb[q * 2 + 0] = f2_to_h2(w.x, w.y);
        hb[q * 2 + 1] = f2_to_h2(w.z, w.w);
    }
    uint4* dsth = (uint4*)(g_protoNh + (size_t)row * D + lane * 16);
    dsth[0] = make_uint4(hb[0], hb[1], hb[2], hb[3]);
    dsth[1] = make_uint4(hb[4], hb[5], hb[6], hb[7]);
}

// =====================================================================
// K2: RAW-e fp16/f32acc mma GEMM [128x1024x512] per CTA + top-2 + gap.
// Key algebra: argmax_k (e . p_k_norm) is invariant to e's scale, so A
// is converted raw fp32 -> fp16 with NO normalization (A-phase is pure
// convert; norms are computed in K3 where the row is re-read anyway).
// 512 threads, 16 warps = 4(M) x 4(N); warp tile 32x32.
// B: 4-stage 16 KB cp.async ring, distance-2 prefetch, 1 barrier/tile.
// =====================================================================
#define FOLD(slot, val, col) do { \
    float _v = (val); int _c = (col); \
    if (_v > tv1[slot]) { tv2[slot] = tv1[slot]; ti2[slot] = ti1[slot]; tv1[slot] = _v; ti1[slot] = _c; } \
    else if (_v > tv2[slot]) { tv2[slot] = _v; ti2[slot] = _c; } \
} while (0)

__global__ void __launch_bounds__(512, 1) k2_mma(const float* __restrict__ emb, int n) {
    extern __shared__ char smem[];
    const uint32_t sbA = smem_u32(smem);
    const uint32_t sbB = sbA + 131072;

    const int tid  = threadIdx.x;
    const int lane = tid & 31;
    const int wid  = tid >> 5;
    const int wm   = wid >> 2;
    const int wn   = wid & 3;
    const int row0 = blockIdx.x * 128;

    // ---- issue B stages 0,1 (tiles idx=0,1): 1024 x 16B each ----
    {
        const char* srcB0 = (const char*)g_protoNh;
        #pragma unroll
        for (int i = 0; i < 2; ++i) {
            int v = tid + i * 512;
            int pr = v >> 3, slot = v & 7;
            CP_ASYNC16(sbB + SWZ((uint32_t)(pr * 128 + slot * 16)),
                       srcB0 + (size_t)pr * 1024 + slot * 16);
        }
        CP_COMMIT();
        const char* srcB1 = (const char*)g_protoNh + 128;
        #pragma unroll
        for (int i = 0; i < 2; ++i) {
            int v = tid + i * 512;
            int pr = v >> 3, slot = v & 7;
            CP_ASYNC16(sbB + 16384u + SWZ((uint32_t)(pr * 128 + slot * 16)),
                       srcB1 + (size_t)pr * 1024 + slot * 16);
        }
        CP_COMMIT();
    }

    // ---- A phase: load raw fp32, convert fp16 (NO normalization) ----
    #pragma unroll 1
    for (int rr = 0; rr < 8; ++rr) {
        int r = wid * 8 + rr;
        int grow = row0 + r;
        const float4* src = (const float4*)(emb + (size_t)grow * D);
        float4 v[4];
        if (grow < n) {
            #pragma unroll
            for (int q = 0; q < 4; ++q) v[q] = src[lane * 4 + q];
        } else {
            #pragma unroll
            for (int q = 0; q < 4; ++q) v[q] = make_float4(0.f, 0.f, 0.f, 0.f);
        }
        uint32_t hb[8];
        #pragma unroll
        for (int q = 0; q < 4; ++q) {
            hb[q * 2 + 0] = f2_to_h2(v[q].x, v[q].y);
            hb[q * 2 + 1] = f2_to_h2(v[q].z, v[q].w);
        }
        #pragma unroll
        for (int h = 0; h < 2; ++h) {
            int s = lane * 2 + h;
            uint32_t off = (uint32_t)(s >> 3) * 16384u + SWZ((uint32_t)(r * 128 + (s & 7) * 16));
            *(uint4*)(smem + off) = make_uint4(hb[h * 4 + 0], hb[h * 4 + 1], hb[h * 4 + 2], hb[h * 4 + 3]);
        }
    }

    float acc[2][4][4];
    float tv1[4], tv2[4];
    int   ti1[4], ti2[4];
    #pragma unroll
    for (int s = 0; s < 4; ++s) { tv1[s] = -3.4e38f; tv2[s] = -3.4e38f; ti1[s] = 0; ti2[s] = 0; }

    uint32_t rbA[2], xA[2], rbB[2], xB[2];
    {
        #pragma unroll
        for (int mf = 0; mf < 2; ++mf) {
            uint32_t rb = (uint32_t)((wm * 32 + mf * 16 + (lane & 15)) * 128 + (lane >> 4) * 16);
            rbA[mf] = rb; xA[mf] = (rb >> 3) & 0x70;
        }
        #pragma unroll
        for (int nh = 0; nh < 2; ++nh) {
            uint32_t rw = (uint32_t)(wn * 32 + nh * 16 + ((lane >> 4) << 3) + (lane & 7));
            uint32_t rb = rw * 128 + (((uint32_t)lane >> 3) & 1u) * 16u;
            rbB[nh] = rb; xB[nh] = (rb >> 3) & 0x70;
        }
    }

    __syncthreads();

    for (int idx = 0; idx < 64; ++idx) {
        const int kc = idx & 7;

        if (idx + 2 < 64) {
            const int nxt = idx + 2;
            const int pt2 = nxt >> 3, kc2 = nxt & 7;
            const char* srcB = (const char*)(g_protoNh + (size_t)(pt2 * 128) * D + kc2 * 64);
            uint32_t base = sbB + (uint32_t)(nxt & 3) * 16384u;
            #pragma unroll
            for (int i = 0; i < 2; ++i) {
                int v = tid + i * 512;
                int pr = v >> 3, slot = v & 7;
                CP_ASYNC16(base + SWZ((uint32_t)(pr * 128 + slot * 16)),
                           srcB + (size_t)pr * 1024 + slot * 16);
            }
            CP_COMMIT();
            CP_WAIT(2);
        } else {
            CP_WAIT(0);
        }
        __syncthreads();

        if (kc == 0) {
            #pragma unroll
            for (int mf = 0; mf < 2; ++mf)
                #pragma unroll
                for (int nf = 0; nf < 4; ++nf)
                    #pragma unroll
                    for (int q = 0; q < 4; ++q) acc[mf][nf][q] = 0.f;
        }

        const uint32_t aBase = sbA + (uint32_t)kc * 16384u;
        const uint32_t bBase = sbB + (uint32_t)(idx & 3) * 16384u;
        #pragma unroll
        for (int ks = 0; ks < 4; ++ks) {
            uint32_t af[2][4], bf[2][4];
            #pragma unroll
            for (int mf = 0; mf < 2; ++mf)
                ldsm_x4(af[mf], aBase + ((rbA[mf] + ks * 32) ^ xA[mf]));
            #pragma unroll
            for (int nh = 0; nh < 2; ++nh)
                ldsm_x4(bf[nh], bBase + ((rbB[nh] + ks * 32) ^ xB[nh]));
            #pragma unroll
            for (int mf = 0; mf < 2; ++mf) {
                #pragma unroll
                for (int nh = 0; nh < 2; ++nh) {
                    mma_f16f32(acc[mf][nh * 2 + 0], af[mf], bf[nh][0], bf[nh][1]);
                    mma_f16f32(acc[mf][nh * 2 + 1], af[mf], bf[nh][2], bf[nh][3]);
                }
            }
        }

        if (kc == 7) {
            const int pt = idx >> 3;
            #pragma unroll
            for (int mf = 0; mf < 2; ++mf) {
                #pragma unroll
                for (int nf = 0; nf < 4; ++nf) {
                    int col = pt * 128 + wn * 32 + nf * 8 + (lane & 3) * 2;
                    FOLD(mf * 2 + 0, acc[mf][nf][0], col);
                    FOLD(mf * 2 + 0, acc[mf][nf][1], col + 1);
                    FOLD(mf * 2 + 1, acc[mf][nf][2], col);
                    FOLD(mf * 2 + 1, acc[mf][nf][3], col + 1);
                }
            }
        }
    }

    // ---- quad reduce + cross-warp merge (top-2) ----
    #pragma unroll
    for (int s = 0; s < 4; ++s) {
        #pragma unroll
        for (int off = 1; off <= 2; off <<= 1) {
            float ov1 = __shfl_xor_sync(0xffffffffu, tv1[s], off);
            int   oi1 = __shfl_xor_sync(0xffffffffu, ti1[s], off);
            float ov2 = __shfl_xor_sync(0xffffffffu, tv2[s], off);
            int   oi2 = __shfl_xor_sync(0xffffffffu, ti2[s], off);
            bool alead = (tv1[s] > ov1) || (tv1[s] == ov1 && ti1[s] < oi1);
            float nv1 = alead ? tv1[s] : ov1;  int ni1 = alead ? ti1[s] : oi1;
            float cv  = alead ? ov1 : tv1[s];  int ci  = alead ? oi1 : ti1[s];
            float sv  = alead ? tv2[s] : ov2;  int si  = alead ? ti2[s] : oi2;
            bool slead = (sv > cv) || (sv == cv && si < ci);
            tv1[s] = nv1; ti1[s] = ni1;
            tv2[s] = slead ? sv : cv; ti2[s] = slead ? si : ci;
        }
    }
    __syncthreads();

    float4* buf = (float4*)(smem + 131072);
    if ((lane & 3) == 0) {
        #pragma unroll
        for (int s = 0; s < 4; ++s) {
            int r = wm * 32 + (s >> 1) * 16 + (lane >> 2) + (s & 1) * 8;
            buf[wn * 128 + r] = make_float4(tv1[s], __int_as_float(ti1[s]),
                                            tv2[s], __int_as_float(ti2[s]));
        }
    }
    __syncthreads();

    if (tid < 128) {
        float4 m = buf[tid];
        float v1 = m.x; int i1 = __float_as_int(m.y);
        float v2 = m.z; int i2 = __float_as_int(m.w);
        #pragma unroll
        for (int w = 1; w < 4; ++w) {
            float4 o = buf[w * 128 + tid];
            float ov1 = o.x; int oi1 = __float_as_int(o.y);
            float ov2 = o.z; int oi2 = __float_as_int(o.w);
            bool alead = (v1 > ov1) || (v1 == ov1 && i1 < oi1);
            float nv1 = alead ? v1 : ov1;  int ni1 = alead ? i1 : oi1;
            float cv  = alead ? ov1 : v1;  int ci  = alead ? oi1 : i1;
            float sv  = alead ? v2 : ov2;  int si  = alead ? i2 : oi2;
            bool slead = (sv > cv) || (sv == cv && si < ci);
            v1 = nv1; i1 = ni1;
            v2 = slead ? sv : cv; i2 = slead ? si : ci;
        }
        int grow = row0 + tid;
        if (grow < n) {
            g_cand[grow * 2 + 0] = i1;
            g_cand[grow * 2 + 1] = i2;
            g_gap[grow] = v1 - v2;   // raw units (scaled by ||e||)
        }
    }
}

// =====================================================================
// K3: norm computation + gap-gated fp32 rescore (top-2) + segment
// accumulation. warp per row; grid n/8 x 256.
// gap_raw * inv >= GAP_TAU (normalized units, ~25 sigma of fp16 GEMM
// noise) certifies top-1; else exact fp32 rescore (scale-invariant).
// =====================================================================
__global__ void k3_rescore_accum(const float* __restrict__ emb, int n) {
    int lane = threadIdx.x & 31;
    int row  = blockIdx.x * 8 + (threadIdx.x >> 5);
    if (row >= n) return;

    int i1 = g_cand[row * 2 + 0];
    int i2 = g_cand[row * 2 + 1];
    float gapr = g_gap[row];

    const float4* e4 = (const float4*)(emb + (size_t)row * D);
    float4 ev[4];
    float ss = 0.f;
    #pragma unroll
    for (int q = 0; q < 4; ++q) {
        ev[q] = e4[q * 32 + lane];
        ss += ev[q].x * ev[q].x + ev[q].y * ev[q].y + ev[q].z * ev[q].z + ev[q].w * ev[q].w;
    }
    #pragma unroll
    for (int o = 16; o; o >>= 1) ss += __shfl_xor_sync(0xffffffffu, ss, o);
    float inv = 1.f / fmaxf(sqrtf(ss), 1e-6f);

    int k = i1;
    if (gapr * inv < GAP_TAU) {
        const float4* p1 = (const float4*)(g_protoN + (size_t)i1 * D);
        const float4* p2 = (const float4*)(g_protoN + (size_t)i2 * D);
        float s1 = 0.f, s2 = 0.f;
        #pragma unroll
        for (int q = 0; q < 4; ++q) {
            float4 a = p1[q * 32 + lane];
            float4 b = p2[q * 32 + lane];
            s1 += ev[q].x * a.x + ev[q].y * a.y + ev[q].z * a.z + ev[q].w * a.w;
            s2 += ev[q].x * b.x + ev[q].y * b.y + ev[q].z * b.z + ev[q].w * b.w;
        }
        #pragma unroll
        for (int o = 16; o; o >>= 1) {
            s1 += __shfl_xor_sync(0xffffffffu, s1, o);
            s2 += __shfl_xor_sync(0xffffffffu, s2, o);
        }
        k = (s2 > s1 || (s2 == s1 && i2 < i1)) ? i2 : i1;
    }

    float4* dst = (float4*)(g_sums + (size_t)k * D);
    #pragma unroll
    for (int q = 0; q < 4; ++q) {
        float4 v = ev[q];
        v.x *= inv; v.y *= inv; v.z *= inv; v.w *= inv;
        atomicAdd(&dst[q * 32 + lane], v);
    }
    if (lane == 0) atomicAdd(&g_counts[k], 1);
}

// =====================================================================
// K4: EMA + renormalize + where(has). Block (128 thr) per prototype row.
// =====================================================================
__global__ void k4_final(const float* __restrict__ protos, float* __restrict__ out) {
    __shared__ float red[4];
    int k   = blockIdx.x;
    int t   = threadIdx.x;
    int lane = t & 31, w = t >> 5;

    int   cnt = g_counts[k];
    float cf  = fmaxf((float)cnt, 1.f);

    float4 pv = *(const float4*)(protos + (size_t)k * D + t * 4);
    float4 sm = *(const float4*)(g_sums + (size_t)k * D + t * 4);
    float4 uv = make_float4(0.9f * pv.x + 0.1f * (sm.x / cf),
                            0.9f * pv.y + 0.1f * (sm.y / cf),
                            0.9f * pv.z + 0.1f * (sm.z / cf),
                            0.9f * pv.w + 0.1f * (sm.w / cf));
    float ss = uv.x * uv.x + uv.y * uv.y + uv.z * uv.z + uv.w * uv.w;
    #pragma unroll
    for (int o = 16; o; o >>= 1) ss += __shfl_xor_sync(0xffffffffu, ss, o);
    if (lane == 0) red[w] = ss;
    __syncthreads();
    ss = red[0] + red[1] + red[2] + red[3];
    float inv = 1.f / fmaxf(sqrtf(ss), 1e-6f);

    float4 o4 = (cnt > 0)
        ? make_float4(uv.x * inv, uv.y * inv, uv.z * inv, uv.w * inv)
        : pv;
    *(float4*)(out + (size_t)k * D + t * 4) = o4;
}

// =====================================================================
extern "C" void kernel_launch(void* const* d_in, const int* in_sizes, int n_in,
                              void* d_out, int out_size) {
    const float* emb    = (const float*)d_in[0];
    const float* protos = (const float*)d_in[1];
    float* out = (float*)d_out;
    int n = in_sizes[0] / D;   // 131072

    const int smem2 = 131072 + 4 * 16384;  // 192 KB
    cudaFuncSetAttribute(k2_mma, cudaFuncAttributeMaxDynamicSharedMemorySize, smem2);

    k1_norm_proto<<<KPROT / 8, 256>>>(protos);
    k2_mma<<<(n + 127) / 128, 512, smem2>>>(emb, n);
    k3_rescore_accum<<<(n + 7) / 8, 256>>>(emb, n);
    k4_final<<<KPROT, 128>>>(protos, out);
}

// round 15
// speedup vs baseline: 1.2417x; 1.1025x over previous
#include <cuda_runtime.h>
#include <cuda_fp16.h>
#include <cstdint>

#define D      512
#define KPROT  1024
#define NMAX   131072
#define GAP_TAU 5e-4f   // applied to gap_raw * invnorm (normalized units)

// ---------------- device scratch ----------------
__device__ float  g_protoN [KPROT * D];   // normalized prototypes fp32 (rescoring)
__device__ __half g_protoNh[KPROT * D];   // normalized prototypes fp16 (GEMM)
__device__ float  g_sums   [KPROT * D];
__device__ int    g_counts [KPROT];
__device__ float  g_gap    [NMAX];        // raw-unit top1-top2 gap from fp16 GEMM
__device__ int    g_cand   [NMAX * 2];    // top-2 candidate protos per row

// ---------------- helpers ----------------
__device__ __forceinline__ uint32_t smem_u32(const void* p) {
    uint32_t a;
    asm("{ .reg .u64 t; cvta.to.shared.u64 t, %1; cvt.u32.u64 %0, t; }" : "=r"(a) : "l"(p));
    return a;
}
#define SWZ(x) ((x) ^ (((x) >> 3) & 0x70))

#define CP_ASYNC16(dst, src) \
    asm volatile("cp.async.cg.shared.global [%0], [%1], 16;" :: "r"(dst), "l"(src))
#define CP_COMMIT() asm volatile("cp.async.commit_group;")
#define CP_WAIT(n)  asm volatile("cp.async.wait_group %0;" :: "n"(n))

__device__ __forceinline__ void ldsm_x4(uint32_t a[4], uint32_t addr) {
    asm volatile("ldmatrix.sync.aligned.m8n8.x4.shared.b16 {%0,%1,%2,%3}, [%4];"
        : "=r"(a[0]), "=r"(a[1]), "=r"(a[2]), "=r"(a[3]) : "r"(addr));
}
// fp16 inputs, f32 accumulate
__device__ __forceinline__ void mma_f16f32(float c[4], const uint32_t a[4], uint32_t b0, uint32_t b1) {
    asm volatile(
        "mma.sync.aligned.m16n8k16.row.col.f32.f16.f16.f32 "
        "{%0,%1,%2,%3},{%4,%5,%6,%7},{%8,%9},{%0,%1,%2,%3};"
        : "+f"(c[0]), "+f"(c[1]), "+f"(c[2]), "+f"(c[3])
        : "r"(a[0]), "r"(a[1]), "r"(a[2]), "r"(a[3]), "r"(b0), "r"(b1));
}
__device__ __forceinline__ uint32_t f2_to_h2(float x, float y) {
    __half2 h = __float22half2_rn(make_float2(x, y));
    return *(uint32_t*)&h;
}

// =====================================================================
// K1: normalize prototypes -> fp32 + fp16; zero sums/counts
// =====================================================================
__global__ void k1_norm_proto(const float* __restrict__ protos) {
    int lane = threadIdx.x & 31;
    int row  = blockIdx.x * 8 + (threadIdx.x >> 5);

    if (blockIdx.x < 4) g_counts[blockIdx.x * 256 + threadIdx.x] = 0;
    {
        float4* s4 = (float4*)g_sums;
        int t = blockIdx.x * 256 + threadIdx.x;
        #pragma unroll
        for (int q = 0; q < 4; ++q) s4[q * 32768 + t] = make_float4(0.f, 0.f, 0.f, 0.f);
    }

    const float4* src = (const float4*)(protos + (size_t)row * D);
    float4 v[4];
    float ss = 0.f;
    #pragma unroll
    for (int q = 0; q < 4; ++q) {
        v[q] = src[lane * 4 + q];
        ss += v[q].x * v[q].x + v[q].y * v[q].y + v[q].z * v[q].z + v[q].w * v[q].w;
    }
    #pragma unroll
    for (int o = 16; o; o >>= 1) ss += __shfl_xor_sync(0xffffffffu, ss, o);
    float inv = 1.f / fmaxf(sqrtf(ss), 1e-6f);

    float4* dstf = (float4*)(g_protoN + (size_t)row * D);
    uint32_t hb[8];
    #pragma unroll
    for (int q = 0; q < 4; ++q) {
        float4 w = make_float4(v[q].x * inv, v[q].y * inv, v[q].z * inv, v[q].w * inv);
        dstf[lane * 4 + q] = w;
        hb[q * 2 + 0] = f2_to_h2(w.x, w.y);
        hb[q * 2 + 1] = f2_to_h2(w.z, w.w);
    }
    uint4* dsth = (uint4*)(g_protoNh + (size_t)row * D + lane * 16);
    dsth[0] = make_uint4(hb[0], hb[1], hb[2], hb[3]);
    dsth[1] = make_uint4(hb[4], hb[5], hb[6], hb[7]);
}

// =====================================================================
// K2: RAW-e fp16/f32acc mma GEMM [64x1024x512] per CTA + top-2 + gap.
// 2 CTAs/SM (occupancy 2): serial phases (A convert, prologue, epilogue)
// overlap the co-resident CTA's MMA stream.
// 256 threads, 8 warps = 2(M) x 4(N); warp tile 32x32.
// A: 64 KB (8 kc-chunks of 8 KB). B: 3-stage 16 KB cp.async ring,
// prefetch issued AFTER the barrier (WAR-safe at distance 2 with 3 stages).
// =====================================================================
#define FOLD(slot, val, col) do { \
    float _v = (val); int _c = (col); \
    if (_v > tv1[slot]) { tv2[slot] = tv1[slot]; ti2[slot] = ti1[slot]; tv1[slot] = _v; ti1[slot] = _c; } \
    else if (_v > tv2[slot]) { tv2[slot] = _v; ti2[slot] = _c; } \
} while (0)

__global__ void __launch_bounds__(256, 2) k2_mma(const float* __restrict__ emb, int n) {
    extern __shared__ char smem[];
    const uint32_t sbA = smem_u32(smem);
    const uint32_t sbB = sbA + 65536;

    const int tid  = threadIdx.x;
    const int lane = tid & 31;
    const int wid  = tid >> 5;
    const int wm   = wid >> 2;   // 0..1 (32 rows each)
    const int wn   = wid & 3;    // 0..3 (32 cols each)
    const int row0 = blockIdx.x * 64;

    // ---- issue B stages 0,1 (tiles idx=0,1): 1024 x 16B each, 4/thread ----
    {
        const char* srcB0 = (const char*)g_protoNh;                 // pt=0,kc=0
        #pragma unroll
        for (int i = 0; i < 4; ++i) {
            int v = tid + i * 256;
            int pr = v >> 3, slot = v & 7;
            CP_ASYNC16(sbB + SWZ((uint32_t)(pr * 128 + slot * 16)),
                       srcB0 + (size_t)pr * 1024 + slot * 16);
        }
        CP_COMMIT();
        const char* srcB1 = (const char*)g_protoNh + 128;           // pt=0,kc=1
        #pragma unroll
        for (int i = 0; i < 4; ++i) {
            int v = tid + i * 256;
            int pr = v >> 3, slot = v & 7;
            CP_ASYNC16(sbB + 16384u + SWZ((uint32_t)(pr * 128 + slot * 16)),
                       srcB1 + (size_t)pr * 1024 + slot * 16);
        }
        CP_COMMIT();
    }

    // ---- A phase: load raw fp32, convert fp16 (no normalization) ----
    // warp per row, 8 rows per warp. Lane owns floats [16l,16l+16) = slots 2l,2l+1.
    #pragma unroll 1
    for (int rr = 0; rr < 8; ++rr) {
        int r = wid * 8 + rr;             // 0..63
        int grow = row0 + r;
        const float4* src = (const float4*)(emb + (size_t)grow * D);
        float4 v[4];
        if (grow < n) {
            #pragma unroll
            for (int q = 0; q < 4; ++q) v[q] = src[lane * 4 + q];
        } else {
            #pragma unroll
            for (int q = 0; q < 4; ++q) v[q] = make_float4(0.f, 0.f, 0.f, 0.f);
        }
        uint32_t hb[8];
        #pragma unroll
        for (int q = 0; q < 4; ++q) {
            hb[q * 2 + 0] = f2_to_h2(v[q].x, v[q].y);
            hb[q * 2 + 1] = f2_to_h2(v[q].z, v[q].w);
        }
        #pragma unroll
        for (int h = 0; h < 2; ++h) {
            int s = lane * 2 + h;         // 16B slot 0..63 within row
            uint32_t off = (uint32_t)(s >> 3) * 8192u + SWZ((uint32_t)(r * 128 + (s & 7) * 16));
            *(uint4*)(smem + off) = make_uint4(hb[h * 4 + 0], hb[h * 4 + 1], hb[h * 4 + 2], hb[h * 4 + 3]);
        }
    }

    float acc[2][4][4];
    float tv1[4], tv2[4];
    int   ti1[4], ti2[4];
    #pragma unroll
    for (int s = 0; s < 4; ++s) { tv1[s] = -3.4e38f; tv2[s] = -3.4e38f; ti1[s] = 0; ti2[s] = 0; }

    // ldmatrix base byte offsets + constant swizzle XORs
    uint32_t rbA[2], xA[2], rbB[2], xB[2];
    {
        #pragma unroll
        for (int mf = 0; mf < 2; ++mf) {
            uint32_t rb = (uint32_t)((wm * 32 + mf * 16 + (lane & 15)) * 128 + (lane >> 4) * 16);
            rbA[mf] = rb; xA[mf] = (rb >> 3) & 0x70;
        }
        #pragma unroll
        for (int nh = 0; nh < 2; ++nh) {
            uint32_t rw = (uint32_t)(wn * 32 + nh * 16 + ((lane >> 4) << 3) + (lane & 7));
            uint32_t rb = rw * 128 + (((uint32_t)lane >> 3) & 1u) * 16u;
            rbB[nh] = rb; xB[nh] = (rb >> 3) & 0x70;
        }
    }

    __syncthreads();   // A visible; B stages 0,1 issued

    for (int idx = 0; idx < 64; ++idx) {
        const int kc = idx & 7;

        if (idx < 63) { CP_WAIT(1); } else { CP_WAIT(0); }
        __syncthreads();

        // issue prefetch for idx+2 AFTER barrier: stage (idx+2)%3's previous
        // readers (iteration idx-1) provably finished before this barrier.
        if (idx + 2 < 64) {
            const int nxt = idx + 2;
            const int pt2 = nxt >> 3, kc2 = nxt & 7;
            const char* srcB = (const char*)(g_protoNh + (size_t)(pt2 * 128) * D + kc2 * 64);
            uint32_t base = sbB + (uint32_t)(nxt % 3) * 16384u;
            #pragma unroll
            for (int i = 0; i < 4; ++i) {
                int v = tid + i * 256;
                int pr = v >> 3, slot = v & 7;
                CP_ASYNC16(base + SWZ((uint32_t)(pr * 128 + slot * 16)),
                           srcB + (size_t)pr * 1024 + slot * 16);
            }
            CP_COMMIT();
        }

        if (kc == 0) {
            #pragma unroll
            for (int mf = 0; mf < 2; ++mf)
                #pragma unroll
                for (int nf = 0; nf < 4; ++nf)
                    #pragma unroll
                    for (int q = 0; q < 4; ++q) acc[mf][nf][q] = 0.f;
        }

        const uint32_t aBase = sbA + (uint32_t)kc * 8192u;
        const uint32_t bBase = sbB + (uint32_t)(idx % 3) * 16384u;
        #pragma unroll
        for (int ks = 0; ks < 4; ++ks) {
            uint32_t af[2][4], bf[2][4];
            #pragma unroll
            for (int mf = 0; mf < 2; ++mf)
                ldsm_x4(af[mf], aBase + ((rbA[mf] + ks * 32) ^ xA[mf]));
            #pragma unroll
            for (int nh = 0; nh < 2; ++nh)
                ldsm_x4(bf[nh], bBase + ((rbB[nh] + ks * 32) ^ xB[nh]));
            #pragma unroll
            for (int mf = 0; mf < 2; ++mf) {
                #pragma unroll
                for (int nh = 0; nh < 2; ++nh) {
                    mma_f16f32(acc[mf][nh * 2 + 0], af[mf], bf[nh][0], bf[nh][1]);
                    mma_f16f32(acc[mf][nh * 2 + 1], af[mf], bf[nh][2], bf[nh][3]);
                }
            }
        }

        if (kc == 7) {
            const int pt = idx >> 3;
            #pragma unroll
            for (int mf = 0; mf < 2; ++mf) {
                #pragma unroll
                for (int nf = 0; nf < 4; ++nf) {
                    int col = pt * 128 + wn * 32 + nf * 8 + (lane & 3) * 2;
                    FOLD(mf * 2 + 0, acc[mf][nf][0], col);
                    FOLD(mf * 2 + 0, acc[mf][nf][1], col + 1);
                    FOLD(mf * 2 + 1, acc[mf][nf][2], col);
                    FOLD(mf * 2 + 1, acc[mf][nf][3], col + 1);
                }
            }
        }
    }

    // ---- quad reduce + cross-warp merge (top-2) ----
    #pragma unroll
    for (int s = 0; s < 4; ++s) {
        #pragma unroll
        for (int off = 1; off <= 2; off <<= 1) {
            float ov1 = __shfl_xor_sync(0xffffffffu, tv1[s], off);
            int   oi1 = __shfl_xor_sync(0xffffffffu, ti1[s], off);
            float ov2 = __shfl_xor_sync(0xffffffffu, tv2[s], off);
            int   oi2 = __shfl_xor_sync(0xffffffffu, ti2[s], off);
            bool alead = (tv1[s] > ov1) || (tv1[s] == ov1 && ti1[s] < oi1);
            float nv1 = alead ? tv1[s] : ov1;  int ni1 = alead ? ti1[s] : oi1;
            float cv  = alead ? ov1 : tv1[s];  int ci  = alead ? oi1 : ti1[s];
            float sv  = alead ? tv2[s] : ov2;  int si  = alead ? ti2[s] : oi2;
            bool slead = (sv > cv) || (sv == cv && si < ci);
            tv1[s] = nv1; ti1[s] = ni1;
            tv2[s] = slead ? sv : cv; ti2[s] = slead ? si : ci;
        }
    }
    __syncthreads();   // done with B smem; reuse for cross-warp merge

    float4* buf = (float4*)(smem + 65536);   // 4 wn-groups x 64 rows x 16B = 4 KB
    if ((lane & 3) == 0) {
        #pragma unroll
        for (int s = 0; s < 4; ++s) {
            int r = wm * 32 + (s >> 1) * 16 + (lane >> 2) + (s & 1) * 8;   // 0..63
            buf[wn * 64 + r] = make_float4(tv1[s], __int_as_float(ti1[s]),
                                           tv2[s], __int_as_float(ti2[s]));
        }
    }
    __syncthreads();

    if (tid < 64) {
        float4 m = buf[tid];
        float v1 = m.x; int i1 = __float_as_int(m.y);
        float v2 = m.z; int i2 = __float_as_int(m.w);
        #pragma unroll
        for (int w = 1; w < 4; ++w) {
            float4 o = buf[w * 64 + tid];
            float ov1 = o.x; int oi1 = __float_as_int(o.y);
            float ov2 = o.z; int oi2 = __float_as_int(o.w);
            bool alead = (v1 > ov1) || (v1 == ov1 && i1 < oi1);
            float nv1 = alead ? v1 : ov1;  int ni1 = alead ? i1 : oi1;
            float cv  = alead ? ov1 : v1;  int ci  = alead ? oi1 : i1;
            float sv  = alead ? v2 : ov2;  int si  = alead ? i2 : oi2;
            bool slead = (sv > cv) || (sv == cv && si < ci);
            v1 = nv1; i1 = ni1;
            v2 = slead ? sv : cv; i2 = slead ? si : ci;
        }
        int grow = row0 + tid;
        if (grow < n) {
            g_cand[grow * 2 + 0] = i1;
            g_cand[grow * 2 + 1] = i2;
            g_gap[grow] = v1 - v2;   // raw units (scaled by ||e||)
        }
    }
}

// =====================================================================
// K3: norm computation + gap-gated fp32 rescore (top-2) + segment
// accumulation. warp per row; grid n/8 x 256.
// =====================================================================
__global__ void k3_rescore_accum(const float* __restrict__ emb, int n) {
    int lane = threadIdx.x & 31;
    int row  = blockIdx.x * 8 + (threadIdx.x >> 5);
    if (row >= n) return;

    int i1 = g_cand[row * 2 + 0];
    int i2 = g_cand[row * 2 + 1];
    float gapr = g_gap[row];

    const float4* e4 = (const float4*)(emb + (size_t)row * D);
    float4 ev[4];
    float ss = 0.f;
    #pragma unroll
    for (int q = 0; q < 4; ++q) {
        ev[q] = e4[q * 32 + lane];
        ss += ev[q].x * ev[q].x + ev[q].y * ev[q].y + ev[q].z * ev[q].z + ev[q].w * ev[q].w;
    }
    #pragma unroll
    for (int o = 16; o; o >>= 1) ss += __shfl_xor_sync(0xffffffffu, ss, o);
    float inv = 1.f / fmaxf(sqrtf(ss), 1e-6f);

    int k = i1;
    if (gapr * inv < GAP_TAU) {
        const float4* p1 = (const float4*)(g_protoN + (size_t)i1 * D);
        const float4* p2 = (const float4*)(g_protoN + (size_t)i2 * D);
        float s1 = 0.f, s2 = 0.f;
        #pragma unroll
        for (int q = 0; q < 4; ++q) {
            float4 a = p1[q * 32 + lane];
            float4 b = p2[q * 32 + lane];
            s1 += ev[q].x * a.x + ev[q].y * a.y + ev[q].z * a.z + ev[q].w * a.w;
            s2 += ev[q].x * b.x + ev[q].y * b.y + ev[q].z * b.z + ev[q].w * b.w;
        }
        #pragma unroll
        for (int o = 16; o; o >>= 1) {
            s1 += __shfl_xor_sync(0xffffffffu, s1, o);
            s2 += __shfl_xor_sync(0xffffffffu, s2, o);
        }
        k = (s2 > s1 || (s2 == s1 && i2 < i1)) ? i2 : i1;
    }

    float4* dst = (float4*)(g_sums + (size_t)k * D);
    #pragma unroll
    for (int q = 0; q < 4; ++q) {
        float4 v = ev[q];
        v.x *= inv; v.y *= inv; v.z *= inv; v.w *= inv;
        atomicAdd(&dst[q * 32 + lane], v);
    }
    if (lane == 0) atomicAdd(&g_counts[k], 1);
}

// =====================================================================
// K4: EMA + renormalize + where(has). Block (128 thr) per prototype row.
// =====================================================================
__global__ void k4_final(const float* __restrict__ protos, float* __restrict__ out) {
    __shared__ float red[4];
    int k   = blockIdx.x;
    int t   = threadIdx.x;
    int lane = t & 31, w = t >> 5;

    int   cnt = g_counts[k];
    float cf  = fmaxf((float)cnt, 1.f);

    float4 pv = *(const float4*)(protos + (size_t)k * D + t * 4);
    float4 sm = *(const float4*)(g_sums + (size_t)k * D + t * 4);
    float4 uv = make_float4(0.9f * pv.x + 0.1f * (sm.x / cf),
                            0.9f * pv.y + 0.1f * (sm.y / cf),
                            0.9f * pv.z + 0.1f * (sm.z / cf),
                            0.9f * pv.w + 0.1f * (sm.w / cf));
    float ss = uv.x * uv.x + uv.y * uv.y + uv.z * uv.z + uv.w * uv.w;
    #pragma unroll
    for (int o = 16; o; o >>= 1) ss += __shfl_xor_sync(0xffffffffu, ss, o);
    if (lane == 0) red[w] = ss;
    __syncthreads();
    ss = red[0] + red[1] + red[2] + red[3];
    float inv = 1.f / fmaxf(sqrtf(ss), 1e-6f);

    float4 o4 = (cnt > 0)
        ? make_float4(uv.x * inv, uv.y * inv, uv.z * inv, uv.w * inv)
        : pv;
    *(float4*)(out + (size_t)k * D + t * 4) = o4;
}

// =====================================================================
extern "C" void kernel_launch(void* const* d_in, const int* in_sizes, int n_in,
                              void* d_out, int out_size) {
    const float* emb    = (const float*)d_in[0];
    const float* protos = (const float*)d_in[1];
    float* out = (float*)d_out;
    int n = in_sizes[0] / D;   // 131072

    const int smem2 = 65536 + 3 * 16384 + 4096;  // A 64K + B ring 48K + merge pad = 116736... keep ring reuse: 112 KB
    const int smem_k2 = 65536 + 3 * 16384;       // 114688 B (merge buf reuses B ring)
    (void)smem2;
    cudaFuncSetAttribute(k2_mma, cudaFuncAttributeMaxDynamicSharedMemorySize, smem_k2);

    k1_norm_proto<<<KPROT / 8, 256>>>(protos);
    k2_mma<<<(n + 63) / 64, 256, smem_k2>>>(emb, n);
    k3_rescore_accum<<<(n + 7) / 8, 256>>>(emb, n);
    k4_final<<<KPROT, 128>>>(protos, out);
}

// round 16
// speedup vs baseline: 1.2701x; 1.0229x over previous
#include <cuda_runtime.h>
#include <cuda_fp16.h>
#include <cstdint>

#define D      512
#define KPROT  1024
#define NMAX   131072
#define GAP_TAU 5e-4f   // applied to gap_raw * invnorm (normalized units)

// ---------------- device scratch ----------------
__device__ float  g_protoN [KPROT * D];   // normalized prototypes fp32 (rescoring)
__device__ __half g_protoNh[KPROT * D];   // normalized prototypes fp16 (GEMM)
__device__ float  g_sums   [KPROT * D];
__device__ int    g_counts [KPROT];

// ---------------- helpers ----------------
__device__ __forceinline__ uint32_t smem_u32(const void* p) {
    uint32_t a;
    asm("{ .reg .u64 t; cvta.to.shared.u64 t, %1; cvt.u32.u64 %0, t; }" : "=r"(a) : "l"(p));
    return a;
}
#define SWZ(x) ((x) ^ (((x) >> 3) & 0x70))

#define CP_ASYNC16(dst, src) \
    asm volatile("cp.async.cg.shared.global [%0], [%1], 16;" :: "r"(dst), "l"(src))
#define CP_COMMIT() asm volatile("cp.async.commit_group;")
#define CP_WAIT(n)  asm volatile("cp.async.wait_group %0;" :: "n"(n))

__device__ __forceinline__ void ldsm_x4(uint32_t a[4], uint32_t addr) {
    asm volatile("ldmatrix.sync.aligned.m8n8.x4.shared.b16 {%0,%1,%2,%3}, [%4];"
        : "=r"(a[0]), "=r"(a[1]), "=r"(a[2]), "=r"(a[3]) : "r"(addr));
}
// fp16 inputs, f32 accumulate
__device__ __forceinline__ void mma_f16f32(float c[4], const uint32_t a[4], uint32_t b0, uint32_t b1) {
    asm volatile(
        "mma.sync.aligned.m16n8k16.row.col.f32.f16.f16.f32 "
        "{%0,%1,%2,%3},{%4,%5,%6,%7},{%8,%9},{%0,%1,%2,%3};"
        : "+f"(c[0]), "+f"(c[1]), "+f"(c[2]), "+f"(c[3])
        : "r"(a[0]), "r"(a[1]), "r"(a[2]), "r"(a[3]), "r"(b0), "r"(b1));
}
__device__ __forceinline__ uint32_t f2_to_h2(float x, float y) {
    __half2 h = __float22half2_rn(make_float2(x, y));
    return *(uint32_t*)&h;
}

// =====================================================================
// K1: normalize prototypes -> fp32 + fp16; zero sums/counts
// =====================================================================
__global__ void k1_norm_proto(const float* __restrict__ protos) {
    int lane = threadIdx.x & 31;
    int row  = blockIdx.x * 8 + (threadIdx.x >> 5);

    if (blockIdx.x < 4) g_counts[blockIdx.x * 256 + threadIdx.x] = 0;
    {
        float4* s4 = (float4*)g_sums;
        int t = blockIdx.x * 256 + threadIdx.x;
        #pragma unroll
        for (int q = 0; q < 4; ++q) s4[q * 32768 + t] = make_float4(0.f, 0.f, 0.f, 0.f);
    }

    const float4* src = (const float4*)(protos + (size_t)row * D);
    float4 v[4];
    float ss = 0.f;
    #pragma unroll
    for (int q = 0; q < 4; ++q) {
        v[q] = src[lane * 4 + q];
        ss += v[q].x * v[q].x + v[q].y * v[q].y + v[q].z * v[q].z + v[q].w * v[q].w;
    }
    #pragma unroll
    for (int o = 16; o; o >>= 1) ss += __shfl_xor_sync(0xffffffffu, ss, o);
    float inv = 1.f / fmaxf(sqrtf(ss), 1e-6f);

    float4* dstf = (float4*)(g_protoN + (size_t)row * D);
    uint32_t hb[8];
    #pragma unroll
    for (int q = 0; q < 4; ++q) {
        float4 w = make_float4(v[q].x * inv, v[q].y * inv, v[q].z * inv, v[q].w * inv);
        dstf[lane * 4 + q] = w;
        hb[q * 2 + 0] = f2_to_h2(w.x, w.y);
        hb[q * 2 + 1] = f2_to_h2(w.z, w.w);
    }
    uint4* dsth = (uint4*)(g_protoNh + (size_t)row * D + lane * 16);
    dsth[0] = make_uint4(hb[0], hb[1], hb[2], hb[3]);
    dsth[1] = make_uint4(hb[4], hb[5], hb[6], hb[7]);
}

// =====================================================================
// K2: fully fused at occupancy 2: RAW-e fp16/f32acc mma GEMM
// [64x1024x512] + top-2 + gap certificate + SELF-CONSUMING epilogue
// (gap-gated fp32 rescore + atomic segment accumulation of this CTA's
// own 64 rows — emb lines L1/L2-hot; sibling CTA's MMA hides it).
// 256 threads, 8 warps = 2(M) x 4(N); warp tile 32x32.
// A: 64 KB (8 kc-chunks of 8 KB). B: 3-stage 16 KB cp.async ring,
// prefetch issued AFTER the barrier (WAR-safe at distance 2, 3 stages).
// =====================================================================
#define FOLD(slot, val, col) do { \
    float _v = (val); int _c = (col); \
    if (_v > tv1[slot]) { tv2[slot] = tv1[slot]; ti2[slot] = ti1[slot]; tv1[slot] = _v; ti1[slot] = _c; } \
    else if (_v > tv2[slot]) { tv2[slot] = _v; ti2[slot] = _c; } \
} while (0)

__global__ void __launch_bounds__(256, 2) k2_mma(const float* __restrict__ emb, int n) {
    extern __shared__ char smem[];
    const uint32_t sbA = smem_u32(smem);
    const uint32_t sbB = sbA + 65536;

    const int tid  = threadIdx.x;
    const int lane = tid & 31;
    const int wid  = tid >> 5;
    const int wm   = wid >> 2;   // 0..1 (32 rows each)
    const int wn   = wid & 3;    // 0..3 (32 cols each)
    const int row0 = blockIdx.x * 64;

    float* invs = (float*)(smem + 114688);          // 64 floats

    // ---- issue B stages 0,1 (tiles idx=0,1): 1024 x 16B each, 4/thread ----
    {
        const char* srcB0 = (const char*)g_protoNh;                 // pt=0,kc=0
        #pragma unroll
        for (int i = 0; i < 4; ++i) {
            int v = tid + i * 256;
            int pr = v >> 3, slot = v & 7;
            CP_ASYNC16(sbB + SWZ((uint32_t)(pr * 128 + slot * 16)),
                       srcB0 + (size_t)pr * 1024 + slot * 16);
        }
        CP_COMMIT();
        const char* srcB1 = (const char*)g_protoNh + 128;           // pt=0,kc=1
        #pragma unroll
        for (int i = 0; i < 4; ++i) {
            int v = tid + i * 256;
            int pr = v >> 3, slot = v & 7;
            CP_ASYNC16(sbB + 16384u + SWZ((uint32_t)(pr * 128 + slot * 16)),
                       srcB1 + (size_t)pr * 1024 + slot * 16);
        }
        CP_COMMIT();
    }

    // ---- A phase: load raw fp32, norm (for gate), fp16 into SW128 smem ----
    #pragma unroll 1
    for (int rr = 0; rr < 8; ++rr) {
        int r = wid * 8 + rr;             // 0..63
        int grow = row0 + r;
        const float4* src = (const float4*)(emb + (size_t)grow * D);
        float4 v[4];
        float ss = 0.f;
        if (grow < n) {
            #pragma unroll
            for (int q = 0; q < 4; ++q) {
                v[q] = src[lane * 4 + q];
                ss += v[q].x * v[q].x + v[q].y * v[q].y + v[q].z * v[q].z + v[q].w * v[q].w;
            }
        } else {
            #pragma unroll
            for (int q = 0; q < 4; ++q) v[q] = make_float4(0.f, 0.f, 0.f, 0.f);
        }
        #pragma unroll
        for (int o = 16; o; o >>= 1) ss += __shfl_xor_sync(0xffffffffu, ss, o);
        if (lane == 0) invs[r] = 1.f / fmaxf(sqrtf(ss), 1e-6f);

        uint32_t hb[8];
        #pragma unroll
        for (int q = 0; q < 4; ++q) {
            hb[q * 2 + 0] = f2_to_h2(v[q].x, v[q].y);
            hb[q * 2 + 1] = f2_to_h2(v[q].z, v[q].w);
        }
        #pragma unroll
        for (int h = 0; h < 2; ++h) {
            int s = lane * 2 + h;         // 16B slot 0..63 within row
            uint32_t off = (uint32_t)(s >> 3) * 8192u + SWZ((uint32_t)(r * 128 + (s & 7) * 16));
            *(uint4*)(smem + off) = make_uint4(hb[h * 4 + 0], hb[h * 4 + 1], hb[h * 4 + 2], hb[h * 4 + 3]);
        }
    }

    float acc[2][4][4];
    float tv1[4], tv2[4];
    int   ti1[4], ti2[4];
    #pragma unroll
    for (int s = 0; s < 4; ++s) { tv1[s] = -3.4e38f; tv2[s] = -3.4e38f; ti1[s] = 0; ti2[s] = 0; }

    // ldmatrix base byte offsets + constant swizzle XORs
    uint32_t rbA[2], xA[2], rbB[2], xB[2];
    {
        #pragma unroll
        for (int mf = 0; mf < 2; ++mf) {
            uint32_t rb = (uint32_t)((wm * 32 + mf * 16 + (lane & 15)) * 128 + (lane >> 4) * 16);
            rbA[mf] = rb; xA[mf] = (rb >> 3) & 0x70;
        }
        #pragma unroll
        for (int nh = 0; nh < 2; ++nh) {
            uint32_t rw = (uint32_t)(wn * 32 + nh * 16 + ((lane >> 4) << 3) + (lane & 7));
            uint32_t rb = rw * 128 + (((uint32_t)lane >> 3) & 1u) * 16u;
            rbB[nh] = rb; xB[nh] = (rb >> 3) & 0x70;
        }
    }

    __syncthreads();   // A + invs visible; B stages 0,1 issued

    for (int idx = 0; idx < 64; ++idx) {
        const int kc = idx & 7;

        if (idx < 63) { CP_WAIT(1); } else { CP_WAIT(0); }
        __syncthreads();

        // prefetch idx+2 AFTER barrier (3-stage ring: WAR-safe)
        if (idx + 2 < 64) {
            const int nxt = idx + 2;
            const int pt2 = nxt >> 3, kc2 = nxt & 7;
            const char* srcB = (const char*)(g_protoNh + (size_t)(pt2 * 128) * D + kc2 * 64);
            uint32_t base = sbB + (uint32_t)(nxt % 3) * 16384u;
            #pragma unroll
            for (int i = 0; i < 4; ++i) {
                int v = tid + i * 256;
                int pr = v >> 3, slot = v & 7;
                CP_ASYNC16(base + SWZ((uint32_t)(pr * 128 + slot * 16)),
                           srcB + (size_t)pr * 1024 + slot * 16);
            }
            CP_COMMIT();
        }

        if (kc == 0) {
            #pragma unroll
            for (int mf = 0; mf < 2; ++mf)
                #pragma unroll
                for (int nf = 0; nf < 4; ++nf)
                    #pragma unroll
                    for (int q = 0; q < 4; ++q) acc[mf][nf][q] = 0.f;
        }

        const uint32_t aBase = sbA + (uint32_t)kc * 8192u;
        const uint32_t bBase = sbB + (uint32_t)(idx % 3) * 16384u;
        #pragma unroll
        for (int ks = 0; ks < 4; ++ks) {
            uint32_t af[2][4], bf[2][4];
            #pragma unroll
            for (int mf = 0; mf < 2; ++mf)
                ldsm_x4(af[mf], aBase + ((rbA[mf] + ks * 32) ^ xA[mf]));
            #pragma unroll
            for (int nh = 0; nh < 2; ++nh)
                ldsm_x4(bf[nh], bBase + ((rbB[nh] + ks * 32) ^ xB[nh]));
            #pragma unroll
            for (int mf = 0; mf < 2; ++mf) {
                #pragma unroll
                for (int nh = 0; nh < 2; ++nh) {
                    mma_f16f32(acc[mf][nh * 2 + 0], af[mf], bf[nh][0], bf[nh][1]);
                    mma_f16f32(acc[mf][nh * 2 + 1], af[mf], bf[nh][2], bf[nh][3]);
                }
            }
        }

        if (kc == 7) {
            const int pt = idx >> 3;
            #pragma unroll
            for (int mf = 0; mf < 2; ++mf) {
                #pragma unroll
                for (int nf = 0; nf < 4; ++nf) {
                    int col = pt * 128 + wn * 32 + nf * 8 + (lane & 3) * 2;
                    FOLD(mf * 2 + 0, acc[mf][nf][0], col);
                    FOLD(mf * 2 + 0, acc[mf][nf][1], col + 1);
                    FOLD(mf * 2 + 1, acc[mf][nf][2], col);
                    FOLD(mf * 2 + 1, acc[mf][nf][3], col + 1);
                }
            }
        }
    }

    // ---- quad reduce + cross-warp merge (top-2) ----
    #pragma unroll
    for (int s = 0; s < 4; ++s) {
        #pragma unroll
        for (int off = 1; off <= 2; off <<= 1) {
            float ov1 = __shfl_xor_sync(0xffffffffu, tv1[s], off);
            int   oi1 = __shfl_xor_sync(0xffffffffu, ti1[s], off);
            float ov2 = __shfl_xor_sync(0xffffffffu, tv2[s], off);
            int   oi2 = __shfl_xor_sync(0xffffffffu, ti2[s], off);
            bool alead = (tv1[s] > ov1) || (tv1[s] == ov1 && ti1[s] < oi1);
            float nv1 = alead ? tv1[s] : ov1;  int ni1 = alead ? ti1[s] : oi1;
            float cv  = alead ? ov1 : tv1[s];  int ci  = alead ? oi1 : ti1[s];
            float sv  = alead ? tv2[s] : ov2;  int si  = alead ? ti2[s] : oi2;
            bool slead = (sv > cv) || (sv == cv && si < ci);
            tv1[s] = nv1; ti1[s] = ni1;
            tv2[s] = slead ? sv : cv; ti2[s] = slead ? si : ci;
        }
    }
    __syncthreads();   // done with B smem; reuse for merge buffers

    float4* buf = (float4*)(smem + 65536);          // 4 wn-groups x 64 rows
    float4* fin = (float4*)(smem + 65536 + 4096);   // final per-row (gap, i1, i2)
    if ((lane & 3) == 0) {
        #pragma unroll
        for (int s = 0; s < 4; ++s) {
            int r = wm * 32 + (s >> 1) * 16 + (lane >> 2) + (s & 1) * 8;   // 0..63
            buf[wn * 64 + r] = make_float4(tv1[s], __int_as_float(ti1[s]),
                                           tv2[s], __int_as_float(ti2[s]));
        }
    }
    __syncthreads();

    if (tid < 64) {
        float4 m = buf[tid];
        float v1 = m.x; int i1 = __float_as_int(m.y);
        float v2 = m.z; int i2 = __float_as_int(m.w);
        #pragma unroll
        for (int w = 1; w < 4; ++w) {
            float4 o = buf[w * 64 + tid];
            float ov1 = o.x; int oi1 = __float_as_int(o.y);
            float ov2 = o.z; int oi2 = __float_as_int(o.w);
            bool alead = (v1 > ov1) || (v1 == ov1 && i1 < oi1);
            float nv1 = alead ? v1 : ov1;  int ni1 = alead ? i1 : oi1;
            float cv  = alead ? ov1 : v1;  int ci  = alead ? oi1 : i1;
            float sv  = alead ? v2 : ov2;  int si  = alead ? i2 : oi2;
            bool slead = (sv > cv) || (sv == cv && si < ci);
            v1 = nv1; i1 = ni1;
            v2 = slead ? sv : cv; i2 = slead ? si : ci;
        }
        fin[tid] = make_float4(v1 - v2, __int_as_float(i1), __int_as_float(i2), 0.f);
    }
    __syncthreads();

    // ---- SELF-CONSUMING epilogue: rescore (gap-gated) + accumulate own rows.
    // Sibling CTA's MMA stream hides this except in the final wave. ----
    #pragma unroll 1
    for (int rr = 0; rr < 8; ++rr) {
        int r = wid * 8 + rr;             // 0..63
        int grow = row0 + r;
        if (grow >= n) continue;

        float4 f = fin[r];
        float gapr = f.x;
        int i1 = __float_as_int(f.y);
        int i2 = __float_as_int(f.z);
        float inv = invs[r];

        const float4* e4 = (const float4*)(emb + (size_t)grow * D);
        float4 ev[4];
        #pragma unroll
        for (int q = 0; q < 4; ++q) ev[q] = e4[q * 32 + lane];

        int k = i1;
        if (gapr * inv < GAP_TAU) {
            const float4* p1 = (const float4*)(g_protoN + (size_t)i1 * D);
            const float4* p2 = (const float4*)(g_protoN + (size_t)i2 * D);
            float s1 = 0.f, s2 = 0.f;
            #pragma unroll
            for (int q = 0; q < 4; ++q) {
                float4 a = p1[q * 32 + lane];
                float4 b = p2[q * 32 + lane];
                s1 += ev[q].x * a.x + ev[q].y * a.y + ev[q].z * a.z + ev[q].w * a.w;
                s2 += ev[q].x * b.x + ev[q].y * b.y + ev[q].z * b.z + ev[q].w * b.w;
            }
            #pragma unroll
            for (int o = 16; o; o >>= 1) {
                s1 += __shfl_xor_sync(0xffffffffu, s1, o);
                s2 += __shfl_xor_sync(0xffffffffu, s2, o);
            }
            k = (s2 > s1 || (s2 == s1 && i2 < i1)) ? i2 : i1;
        }

        float4* dst = (float4*)(g_sums + (size_t)k * D);
        #pragma unroll
        for (int q = 0; q < 4; ++q) {
            float4 v = ev[q];
            v.x *= inv; v.y *= inv; v.z *= inv; v.w *= inv;
            atomicAdd(&dst[q * 32 + lane], v);
        }
        if (lane == 0) atomicAdd(&g_counts[k], 1);
    }
}

// =====================================================================
// K4: EMA + renormalize + where(has). Block (128 thr) per prototype row.
// =====================================================================
__global__ void k4_final(const float* __restrict__ protos, float* __restrict__ out) {
    __shared__ float red[4];
    int k   = blockIdx.x;
    int t   = threadIdx.x;
    int lane = t & 31, w = t >> 5;

    int   cnt = g_counts[k];
    float cf  = fmaxf((float)cnt, 1.f);

    float4 pv = *(const float4*)(protos + (size_t)k * D + t * 4);
    float4 sm = *(const float4*)(g_sums + (size_t)k * D + t * 4);
    float4 uv = make_float4(0.9f * pv.x + 0.1f * (sm.x / cf),
                            0.9f * pv.y + 0.1f * (sm.y / cf),
                            0.9f * pv.z + 0.1f * (sm.z / cf),
                            0.9f * pv.w + 0.1f * (sm.w / cf));
    float ss = uv.x * uv.x + uv.y * uv.y + uv.z * uv.z + uv.w * uv.w;
    #pragma unroll
    for (int o = 16; o; o >>= 1) ss += __shfl_xor_sync(0xffffffffu, ss, o);
    if (lane == 0) red[w] = ss;
    __syncthreads();
    ss = red[0] + red[1] + red[2] + red[3];
    float inv = 1.f / fmaxf(sqrtf(ss), 1e-6f);

    float4 o4 = (cnt > 0)
        ? make_float4(uv.x * inv, uv.y * inv, uv.z * inv, uv.w * inv)
        : pv;
    *(float4*)(out + (size_t)k * D + t * 4) = o4;
}

// =====================================================================
extern "C" void kernel_launch(void* const* d_in, const int* in_sizes, int n_in,
                              void* d_out, int out_size) {
    const float* emb    = (const float*)d_in[0];
    const float* protos = (const float*)d_in[1];
    float* out = (float*)d_out;
    int n = in_sizes[0] / D;   // 131072

    const int smem_k2 = 65536 + 3 * 16384 + 256;   // A + B ring + invs = 114944 B
    cudaFuncSetAttribute(k2_mma, cudaFuncAttributeMaxDynamicSharedMemorySize, smem_k2);

    k1_norm_proto<<<KPROT / 8, 256>>>(protos);
    k2_mma<<<(n + 63) / 64, 256, smem_k2>>>(emb, n);
    k4_final<<<KPROT, 128>>>(protos, out);
}